// round 12
// baseline (speedup 1.0000x reference)
#include <cuda_runtime.h>
#include <cuda_bf16.h>
#include <cstdint>

// ===========================================================================
// Problem constants
// ===========================================================================
static constexpr int B  = 16;
static constexpr int H  = 128;
static constexpr int W  = 128;
static constexpr int C  = 64;
static constexpr int NTOT = B * H * W * C;    // 16,777,216
static constexpr float DT  = 0.2f;
static constexpr float EPS = 1e-3f;

// Scratch
__device__ float d_f_buf[NTOT];               // conv1 output (f == h_init)
// Pre-split bf16 weights: [conv][ty][plane(hi=0,lo=1)*12800 + n*200 + k]
__device__ __nv_bfloat16 d_wbf[2][3][2 * 64 * 200];

// ===========================================================================
// PTX helpers (plain-PTX, valid on .target sm_103)
// ===========================================================================
__device__ __forceinline__ uint32_t smem_u32(const void* p) {
    uint32_t a;
    asm("{ .reg .u64 t; cvta.to.shared.u64 t, %1; cvt.u32.u64 %0, t; }"
        : "=r"(a) : "l"(p));
    return a;
}

__device__ __forceinline__ void ldsm_x4(uint32_t (&r)[4], uint32_t addr) {
    asm volatile("ldmatrix.sync.aligned.m8n8.x4.shared.b16 {%0,%1,%2,%3}, [%4];"
                 : "=r"(r[0]), "=r"(r[1]), "=r"(r[2]), "=r"(r[3]) : "r"(addr));
}

__device__ __forceinline__ void mma_bf16(float (&d)[4], const uint32_t (&a)[4],
                                         uint32_t b0, uint32_t b1) {
    asm volatile(
        "mma.sync.aligned.m16n8k16.row.col.f32.bf16.bf16.f32 "
        "{%0,%1,%2,%3}, {%4,%5,%6,%7}, {%8,%9}, {%0,%1,%2,%3};"
        : "+f"(d[0]), "+f"(d[1]), "+f"(d[2]), "+f"(d[3])
        : "r"(a[0]), "r"(a[1]), "r"(a[2]), "r"(a[3]), "r"(b0), "r"(b1));
}

__device__ __forceinline__ void cp_async16(uint32_t saddr, const void* gaddr) {
    asm volatile("cp.async.cg.shared.global [%0], [%1], 16;"
                 :: "r"(saddr), "l"(gaddr) : "memory");
}
__device__ __forceinline__ void cp_commit() {
    asm volatile("cp.async.commit_group;" ::: "memory");
}
template <int N>
__device__ __forceinline__ void cp_wait() {
    asm volatile("cp.async.wait_group %0;" :: "n"(N) : "memory");
}

__device__ __forceinline__ uint32_t bf2_bits(__nv_bfloat162 v) {
    uint32_t u;
    memcpy(&u, &v, 4);
    return u;
}

// ===========================================================================
// Weight prep: HWIO [3][3][64][64] -> per-ty [N=64][K=192] bf16 hi/lo split,
// rows padded to 200 bf16 (400 B).
// ===========================================================================
__global__ void prep_weights(const float* __restrict__ fw,
                             const float* __restrict__ gw)
{
    int idx = blockIdx.x * blockDim.x + threadIdx.x;     // 2*3*192*64 = 73728
    if (idx >= 73728) return;
    int conv = idx / 36864;  int r = idx - conv * 36864;
    int ty   = r / 12288;    r -= ty * 12288;
    int k    = r >> 6;       int n = r & 63;             // k 0..191, n = cout
    int tx   = k >> 6;       int ci = k & 63;
    const float* w = conv ? gw : fw;
    float v = w[(((ty * 3 + tx) * 64) + ci) * 64 + n];
    __nv_bfloat16 hi = __float2bfloat16_rn(v);
    __nv_bfloat16 lo = __float2bfloat16_rn(v - __bfloat162float(hi));
    __nv_bfloat16* base = &d_wbf[conv][ty][0];
    base[n * 200 + k]         = hi;
    base[12800 + n * 200 + k] = lo;
}

// ===========================================================================
// Conv v4.1: 2 output rows per block (M=256), mma.sync bf16 3-pass.
// Grid (64, 16); 512 threads / 16 warps as 8(m) x 2(n): warp tile m32 x n32.
// A: rows y0-1..y0+2 in 3 rotating slots; B: 2 cp.async double-buffered.
// SMEM: 3 * 18720 + 2 * 25600 bf16 = 214,720 B -> 1 CTA/SM.
// ===========================================================================
static constexpr int A_STRIDE = 72;
static constexpr int A_PLANE  = 130 * A_STRIDE;           // 9360 bf16
static constexpr int A_SLOT   = 2 * A_PLANE;              // hi+lo, 18720 bf16
static constexpr int B_PLANE  = 64 * 200;                 // 12800 bf16
static constexpr int B_TY     = 2 * B_PLANE;              // 25600 bf16 per ty
static constexpr int CONV_SMEM_BYTES = (3 * A_SLOT + 2 * B_TY) * 2;  // 214,720
static constexpr int CT = 512;

__global__ __launch_bounds__(CT, 1)
void conv_mma(const float* __restrict__ in,
              const __nv_bfloat16* __restrict__ wbase,    // d_wbf[conv]
              const float* __restrict__ gamma,
              const float* __restrict__ beta,
              const float* __restrict__ mean,
              const float* __restrict__ var,
              float* __restrict__ out)
{
    extern __shared__ __align__(16) char smem_raw[];
    __nv_bfloat16* s_a = reinterpret_cast<__nv_bfloat16*>(smem_raw);   // 3 slots
    __nv_bfloat16* s_b = s_a + 3 * A_SLOT;                             // 2 bufs
    __shared__ float s_scale[64], s_shift[64];

    const int tid  = threadIdx.x;
    const int wid  = tid >> 5;
    const int lane = tid & 31;
    const int y0   = blockIdx.x * 2;
    const int b    = blockIdx.y;
    const int wm   = wid & 7;        // m32 tile over 256 px
    const int wn   = wid >> 3;       // n32 tile over 64 couts
    const int r_out = wm >> 2;       // output row within block (0/1)
    const int xw    = (wm & 3) * 32; // x offset of warp tile

    if (tid < 64) {
        float sc = gamma[tid] * rsqrtf(var[tid] + EPS);
        s_scale[tid] = sc;
        s_shift[tid] = beta[tid] - mean[tid] * sc;
    }

    const uint32_t a_base0 = smem_u32(s_a);
    const uint32_t b_base  = smem_u32(s_b);

    // ---- issue cp.async for B ty=0 (buf0, group0) and ty=1 (buf1, group1) ----
#pragma unroll
    for (int tyg = 0; tyg < 2; ++tyg) {
        const char* src = reinterpret_cast<const char*>(wbase + tyg * B_TY);
        const uint32_t dst = b_base + (uint32_t)tyg * (B_TY * 2);
#pragma unroll
        for (int q = 0; q < 7; ++q) {
            int idx = tid + q * CT;
            if (idx < 3200) cp_async16(dst + idx * 16, src + idx * 16);
        }
        cp_commit();
    }

    const float* inb = in + ((size_t)b * H) * W * C;

    const int r8  = lane & 7;
    const int sel = lane >> 3;
    const int a_row_off = (sel & 1) * 8 + r8;
    const int a_kh      = (sel >> 1) * 16;
    const int b_n_off   = (sel >> 1) * 8 + r8;
    const int b_kh      = (sel & 1) * 16;

    // ---- prefetch input row y0+2 (4th row) into registers ----
    float4 pr[5];
    {
        const int yy = y0 + 2;
        const bool rowok = (unsigned)yy < (unsigned)H;
#pragma unroll
        for (int q = 0; q < 5; ++q) {
            const int e = tid + q * CT;
            pr[q] = make_float4(0.f, 0.f, 0.f, 0.f);
            if (e < 2080) {
                const int px = e >> 4;
                const int c4 = (e & 15) << 2;
                if (rowok && px >= 1 && px <= 128)
                    pr[q] = *reinterpret_cast<const float4*>(
                        inb + ((size_t)yy * W + (px - 1)) * C + c4);
            }
        }
    }
    __syncthreads();   // s_scale/s_shift ready

    // ---- stage input rows y0-1, y0, y0+1 into slots 0,1,2 ----
#pragma unroll
    for (int q = 0; q < 13; ++q) {
        const int idx = tid + q * CT;
        if (idx >= 6240) break;
        const int r  = idx / 2080;
        const int e  = idx - r * 2080;
        const int px = e >> 4;
        const int c4 = (e & 15) << 2;
        const int yy = y0 - 1 + r;
        float v0 = 0.f, v1 = 0.f, v2 = 0.f, v3 = 0.f;
        if ((unsigned)yy < (unsigned)H && px >= 1 && px <= 128) {
            float4 t = *reinterpret_cast<const float4*>(
                inb + ((size_t)yy * W + (px - 1)) * C + c4);
            v0 = fmaxf(fmaf(t.x, s_scale[c4],     s_shift[c4]),     0.f);
            v1 = fmaxf(fmaf(t.y, s_scale[c4 + 1], s_shift[c4 + 1]), 0.f);
            v2 = fmaxf(fmaf(t.z, s_scale[c4 + 2], s_shift[c4 + 2]), 0.f);
            v3 = fmaxf(fmaf(t.w, s_scale[c4 + 3], s_shift[c4 + 3]), 0.f);
        }
        __nv_bfloat162 h01 = __floats2bfloat162_rn(v0, v1);
        __nv_bfloat162 h23 = __floats2bfloat162_rn(v2, v3);
        __nv_bfloat162 l01 = __floats2bfloat162_rn(
            v0 - __bfloat162float(h01.x), v1 - __bfloat162float(h01.y));
        __nv_bfloat162 l23 = __floats2bfloat162_rn(
            v2 - __bfloat162float(h23.x), v3 - __bfloat162float(h23.y));
        __nv_bfloat16* slot = s_a + r * A_SLOT;
        const int o = px * A_STRIDE + c4;
        *reinterpret_cast<uint2*>(slot + o) = make_uint2(bf2_bits(h01), bf2_bits(h23));
        *reinterpret_cast<uint2*>(slot + A_PLANE + o) = make_uint2(bf2_bits(l01), bf2_bits(l23));
    }
    cp_wait<0>();      // B0, B1 arrived
    __syncthreads();

    float acc[2][4][4];            // [m16 half][n8 quarter]
#pragma unroll
    for (int mt = 0; mt < 2; ++mt)
#pragma unroll
        for (int nt = 0; nt < 4; ++nt)
#pragma unroll
            for (int e = 0; e < 4; ++e) acc[mt][nt][e] = 0.f;

    // ---------------- mma over 3 ty ----------------
#pragma unroll
    for (int ty = 0; ty < 3; ++ty) {
        int slot = r_out + ty;           // input row index
        if (slot >= 3) slot -= 3;        // rotating slot
        const uint32_t ah_base = a_base0 + (uint32_t)slot * (A_SLOT * 2);
        const uint32_t al_base = ah_base + A_PLANE * 2;
        const int bbuf = (ty == 1) ? 1 : 0;          // ty0->buf0, ty1->buf1, ty2->buf0
        const uint32_t bh_base = b_base + (uint32_t)bbuf * (B_TY * 2);
        const uint32_t bl_base = bh_base + B_PLANE * 2;

#pragma unroll
        for (int ks = 0; ks < 12; ++ks) {
            const int tx   = ks >> 2;
            const int ci16 = ks & 3;

            uint32_t afr[2][2][4];     // [m16 half][plane]
#pragma unroll
            for (int mt = 0; mt < 2; ++mt) {
                const int px = xw + mt * 16 + a_row_off + tx;
                const uint32_t off = (uint32_t)(px * (A_STRIDE * 2) + ci16 * 32 + a_kh);
                ldsm_x4(afr[mt][0], ah_base + off);
                ldsm_x4(afr[mt][1], al_base + off);
            }
            uint32_t bfr[2][2][4];     // [n16 group][plane]
#pragma unroll
            for (int g = 0; g < 2; ++g) {
                const int n = wn * 32 + g * 16 + b_n_off;
                const uint32_t off = (uint32_t)(n * 400 + tx * 128 + ci16 * 32 + b_kh);
                ldsm_x4(bfr[g][0], bh_base + off);
                ldsm_x4(bfr[g][1], bl_base + off);
            }
#pragma unroll
            for (int mt = 0; mt < 2; ++mt)
#pragma unroll
                for (int nt = 0; nt < 4; ++nt) {
                    const int g = nt >> 1, h2 = (nt & 1) * 2;
                    mma_bf16(acc[mt][nt], afr[mt][0], bfr[g][0][h2], bfr[g][0][h2 + 1]);
                    mma_bf16(acc[mt][nt], afr[mt][0], bfr[g][1][h2], bfr[g][1][h2 + 1]);
                    mma_bf16(acc[mt][nt], afr[mt][1], bfr[g][0][h2], bfr[g][0][h2 + 1]);
                }
        }

        if (ty == 0) {
            // slot0 (row y0-1) dead; B buf0 dead. Refill both for ty=2.
            __syncthreads();
            // transform prefetched row y0+2 into slot 0
            const int yy = y0 + 2;
            const bool rowok = (unsigned)yy < (unsigned)H;
#pragma unroll
            for (int q = 0; q < 5; ++q) {
                const int e = tid + q * CT;
                if (e >= 2080) break;
                const int px = e >> 4;
                const int c4 = (e & 15) << 2;
                float v0 = 0.f, v1 = 0.f, v2 = 0.f, v3 = 0.f;
                if (rowok && px >= 1 && px <= 128) {
                    v0 = fmaxf(fmaf(pr[q].x, s_scale[c4],     s_shift[c4]),     0.f);
                    v1 = fmaxf(fmaf(pr[q].y, s_scale[c4 + 1], s_shift[c4 + 1]), 0.f);
                    v2 = fmaxf(fmaf(pr[q].z, s_scale[c4 + 2], s_shift[c4 + 2]), 0.f);
                    v3 = fmaxf(fmaf(pr[q].w, s_scale[c4 + 3], s_shift[c4 + 3]), 0.f);
                }
                __nv_bfloat162 h01 = __floats2bfloat162_rn(v0, v1);
                __nv_bfloat162 h23 = __floats2bfloat162_rn(v2, v3);
                __nv_bfloat162 l01 = __floats2bfloat162_rn(
                    v0 - __bfloat162float(h01.x), v1 - __bfloat162float(h01.y));
                __nv_bfloat162 l23 = __floats2bfloat162_rn(
                    v2 - __bfloat162float(h23.x), v3 - __bfloat162float(h23.y));
                __nv_bfloat16* slot0 = s_a;
                const int o = px * A_STRIDE + c4;
                *reinterpret_cast<uint2*>(slot0 + o) =
                    make_uint2(bf2_bits(h01), bf2_bits(h23));
                *reinterpret_cast<uint2*>(slot0 + A_PLANE + o) =
                    make_uint2(bf2_bits(l01), bf2_bits(l23));
            }
            // B ty=2 into buf0 (group2)
            {
                const char* src = reinterpret_cast<const char*>(wbase + 2 * B_TY);
                const uint32_t dst = b_base;
#pragma unroll
                for (int q = 0; q < 7; ++q) {
                    int idx = tid + q * CT;
                    if (idx < 3200) cp_async16(dst + idx * 16, src + idx * 16);
                }
                cp_commit();
            }
            // ty=1 uses slot1/slot2 + buf1: all ready; no barrier needed here.
        } else if (ty == 1) {
            cp_wait<0>();      // B2 arrived
            __syncthreads();   // slot0 rewrite + B2 visible to all
        }
    }

    // ---- epilogue: fp32 accumulators -> NHWC output ----
    const int ygl = y0 + r_out;
    float* ob = out + (((size_t)b * H + ygl) * W) * C;
#pragma unroll
    for (int mt = 0; mt < 2; ++mt) {
        const int x0 = xw + mt * 16 + (lane >> 2);
        float* row0 = ob + (size_t)x0 * C;
        float* row1 = row0 + 8 * C;
#pragma unroll
        for (int nt = 0; nt < 4; ++nt) {
            const int co = wn * 32 + nt * 8 + (lane & 3) * 2;
            *reinterpret_cast<float2*>(row0 + co) = make_float2(acc[mt][nt][0], acc[mt][nt][1]);
            *reinterpret_cast<float2*>(row1 + co) = make_float2(acc[mt][nt][2], acc[mt][nt][3]);
        }
    }
}

// ===========================================================================
// Fused diffusion v3: channel-pair mapping, coefficients in registers,
// Sobel rows fm/fp staged in SMEM via coalesced float4 loads (was 48
// scattered LDG.64 per thread -> 8 LDG.128 + conflict-free LDS).
// SMEM: P0, P1, BX, BY, FM, FP = 6 x 32 KB = 196,608 B.
// ===========================================================================
static constexpr int DIFF_SMEM_BYTES = 6 * 8192 * 4;   // 196,608 B

__global__ __launch_bounds__(512, 1)
void diffuse_fused(const float* __restrict__ f,
                   float* __restrict__ outh,
                   const float* __restrict__ g,
                   const float* __restrict__ gamma,
                   const float* __restrict__ beta,
                   const float* __restrict__ mean,
                   const float* __restrict__ var)
{
    extern __shared__ float sm[];
    float* P0 = sm;              // F, then h ping
    float* P1 = sm + 8192;       // G, then h pong
    float* BX = sm + 16384;      // 2*DT*Dx
    float* BY = sm + 24576;      // 2*DT*Dy
    float* FM = sm + 32768;      // f row ym (reflected)
    float* FP = sm + 40960;      // f row yp (reflected)
    __shared__ float sc[64], sh[64];

    const int tid = threadIdx.x;
    const int y   = blockIdx.x;
    const int b   = blockIdx.y;

    if (tid < 64) {
        float s = gamma[tid] * rsqrtf(var[tid] + EPS);
        sc[tid] = s;
        sh[tid] = beta[tid] - mean[tid] * s;
    }

    const size_t rowbase = (((size_t)b * H) + y) * W * C;
    const float* frow = f + rowbase;
    const float* grow = g + rowbase;
    const int ym = (y == 0) ? 1 : y - 1;
    const int yp = (y == H - 1) ? H - 2 : y + 1;
    const float* fm = f + ((((size_t)b * H) + ym) * W) * C;
    const float* fp = f + ((((size_t)b * H) + yp) * W) * C;

#pragma unroll
    for (int q = 0; q < 4; ++q) {
        const int idx = (tid + q * 512) * 4;
        *reinterpret_cast<float4*>(P0 + idx) = *reinterpret_cast<const float4*>(frow + idx);
        *reinterpret_cast<float4*>(P1 + idx) = *reinterpret_cast<const float4*>(grow + idx);
        *reinterpret_cast<float4*>(FM + idx) = *reinterpret_cast<const float4*>(fm + idx);
        *reinterpret_cast<float4*>(FP + idx) = *reinterpret_cast<const float4*>(fp + idx);
    }
    __syncthreads();

    const int c = (tid & 31) * 2;
    const float2 sc2 = make_float2(sc[c], sc[c + 1]);
    const float2 sh2 = make_float2(sh[c], sh[c + 1]);

    float2 hprev[8], hcur[8], E2r[8], axr[8], cdr[8], cfr[8];

#pragma unroll
    for (int j = 0; j < 8; ++j) {
        const int i = (tid + j * 512) * 2;
        const int x = i >> 6;
        const int xm = (x == 0) ? 1 : x - 1;
        const int xp = (x == W - 1) ? W - 2 : x + 1;

        const float2 f2 = *reinterpret_cast<const float2*>(P0 + i);
        const float2 g2 = *reinterpret_cast<const float2*>(P1 + i);

        const float2 am = *reinterpret_cast<const float2*>(FM + xm * 64 + c);
        const float2 a0 = *reinterpret_cast<const float2*>(FM + x  * 64 + c);
        const float2 ap = *reinterpret_cast<const float2*>(FM + xp * 64 + c);
        const float2 bm = *reinterpret_cast<const float2*>(FP + xm * 64 + c);
        const float2 b0 = *reinterpret_cast<const float2*>(FP + x  * 64 + c);
        const float2 bp = *reinterpret_cast<const float2*>(FP + xp * 64 + c);
        const float2 fxm = *reinterpret_cast<const float2*>(P0 + xm * 64 + c);
        const float2 fxp = *reinterpret_cast<const float2*>(P0 + xp * 64 + c);

        float dyx = (bm.x + 2.f * b0.x + bp.x) - (am.x + 2.f * a0.x + ap.x);
        float dyy = (bm.y + 2.f * b0.y + bp.y) - (am.y + 2.f * a0.y + ap.y);
        float dxx = (ap.x - am.x) + 2.f * (fxp.x - fxm.x) + (bp.x - bm.x);
        float dxy = (ap.y - am.y) + 2.f * (fxp.y - fxm.y) + (bp.y - bm.y);

        float bxx = (2.f * DT) / (0.25f * dyx * dyx + 1.f);
        float bxy = (2.f * DT) / (0.25f * dyy * dyy + 1.f);
        float byx = (2.f * DT) / (0.25f * dxx * dxx + 1.f);
        float byy = (2.f * DT) / (0.25f * dxy * dxy + 1.f);
        *reinterpret_cast<float2*>(BX + i) = make_float2(bxx, bxy);
        *reinterpret_cast<float2*>(BY + i) = make_float2(byx, byy);

        cdr[j] = make_float2(1.f / (1.f + bxx + byx), 1.f / (1.f + bxy + byy));
        axr[j] = make_float2(DT * g2.x, DT * g2.y);
        cfr[j] = make_float2(2.f * DT * f2.x, 2.f * DT * f2.y);
        hprev[j] = f2;
        hcur[j]  = f2;

        const int ixm = (i + 8192 - 64) & 8191;
        const int ixp = (i + 64) & 8191;
        const float2 gxm = *reinterpret_cast<const float2*>(P1 + ixm);
        const float2 gxp = *reinterpret_cast<const float2*>(P1 + ixp);
        const float gcm = P1[(i & ~63) | ((c + 63) & 63)];
        const float gcp = P1[(i & ~63) | ((c + 2) & 63)];
        E2r[j].x = DT * ((gxm.x - gxp.x) + (gcm - g2.y));
        E2r[j].y = DT * ((gxm.y - gxp.y) + (g2.x - gcp));
    }
    __syncthreads();

#pragma unroll
    for (int k = 0; k < 5; ++k) {
        float* rb = (k & 1) ? P1 : P0;
        float* wb = (k & 1) ? P0 : P1;
#pragma unroll
        for (int j = 0; j < 8; ++j) {
            const int i = (tid + j * 512) * 2;
            const int ixm = (i + 8192 - 64) & 8191;
            const int ixp = (i + 64) & 8191;
            const float2 bx2 = *reinterpret_cast<const float2*>(BX + i);
            const float2 by2 = *reinterpret_cast<const float2*>(BY + i);
            const float2 rxm = *reinterpret_cast<const float2*>(rb + ixm);
            const float2 rxp = *reinterpret_cast<const float2*>(rb + ixp);
            const float rcm = rb[(i & ~63) | ((c + 63) & 63)];
            const float rcp = rb[(i & ~63) | ((c + 2) & 63)];
            const float2 hc = hcur[j];
            const float2 ax = axr[j];

            float s0 = (1.f - bx2.x - by2.x) * hprev[j].x;
            s0 = fmaf(-E2r[j].x, hc.x, s0);
            s0 = fmaf(bx2.x, rxm.x + rxp.x, s0);
            s0 = fmaf(ax.x,  rxp.x - rxm.x, s0);
            s0 = fmaf(by2.x, rcm + hc.y, s0);
            s0 = fmaf(ax.x,  hc.y - rcm, s0);
            s0 = (s0 + cfr[j].x) * cdr[j].x;

            float s1 = (1.f - bx2.y - by2.y) * hprev[j].y;
            s1 = fmaf(-E2r[j].y, hc.y, s1);
            s1 = fmaf(bx2.y, rxm.y + rxp.y, s1);
            s1 = fmaf(ax.y,  rxp.y - rxm.y, s1);
            s1 = fmaf(by2.y, hc.x + rcp, s1);
            s1 = fmaf(ax.y,  rcp - hc.x, s1);
            s1 = (s1 + cfr[j].y) * cdr[j].y;

            hprev[j] = hc;
            hcur[j]  = make_float2(s0, s1);
            if (k < 4) *reinterpret_cast<float2*>(wb + i) = hcur[j];
        }
        if (k < 4) __syncthreads();
    }

    float* o = outh + rowbase;
#pragma unroll
    for (int j = 0; j < 8; ++j) {
        const int i = (tid + j * 512) * 2;
        float2 r = make_float2(fmaxf(fmaf(hcur[j].x, sc2.x, sh2.x), 0.f),
                               fmaxf(fmaf(hcur[j].y, sc2.y, sh2.y), 0.f));
        *reinterpret_cast<float2*>(o + i) = r;
    }
}

// ===========================================================================
extern "C" void kernel_launch(void* const* d_in, const int* in_sizes, int n_in,
                              void* d_out, int out_size)
{
    const float* x   = (const float*)d_in[0];
    const float* f_w = (const float*)d_in[1];
    const float* g_w = (const float*)d_in[2];
    const float* bnf_gamma = (const float*)d_in[3];
    const float* bnf_beta  = (const float*)d_in[4];
    const float* bnf_mean  = (const float*)d_in[5];
    const float* bnf_var   = (const float*)d_in[6];
    const float* bng_gamma = (const float*)d_in[7];
    const float* bng_beta  = (const float*)d_in[8];
    const float* bng_mean  = (const float*)d_in[9];
    const float* bng_var   = (const float*)d_in[10];
    const float* bno_gamma = (const float*)d_in[11];
    const float* bno_beta  = (const float*)d_in[12];
    const float* bno_mean  = (const float*)d_in[13];
    const float* bno_var   = (const float*)d_in[14];

    float* out = (float*)d_out;            // [0:N) = h, [N:2N) = g

    float* fptr = nullptr;
    cudaGetSymbolAddress((void**)&fptr, d_f_buf);
    __nv_bfloat16* wptr = nullptr;
    cudaGetSymbolAddress((void**)&wptr, d_wbf);

    cudaFuncSetAttribute(conv_mma,
                         cudaFuncAttributeMaxDynamicSharedMemorySize, CONV_SMEM_BYTES);
    cudaFuncSetAttribute(diffuse_fused,
                         cudaFuncAttributeMaxDynamicSharedMemorySize, DIFF_SMEM_BYTES);

    // 1) weight transform (both convs)
    prep_weights<<<288, 256>>>(f_w, g_w);

    dim3 cgrid(H / 2, B);

    // 2) f = conv(relu(bn_f(x)), f_w)
    conv_mma<<<cgrid, CT, CONV_SMEM_BYTES>>>(
        x, wptr, bnf_gamma, bnf_beta, bnf_mean, bnf_var, fptr);

    // 3) g = conv(relu(bn_g(f)), g_w) -> d_out[N:2N)
    conv_mma<<<cgrid, CT, CONV_SMEM_BYTES>>>(
        fptr, wptr + 3 * B_TY, bng_gamma, bng_beta, bng_mean, bng_var, out + NTOT);

    // 4) fused sobel + coefficients + 5 diffusion iters + bn_o/relu -> d_out[0:N)
    dim3 dgrid(H, B);
    diffuse_fused<<<dgrid, 512, DIFF_SMEM_BYTES>>>(
        fptr, out, out + NTOT, bno_gamma, bno_beta, bno_mean, bno_var);
}

// round 13
// speedup vs baseline: 1.2018x; 1.2018x over previous
#include <cuda_runtime.h>
#include <cuda_fp16.h>
#include <cstdint>

// ===========================================================================
// Problem constants
// ===========================================================================
static constexpr int B  = 16;
static constexpr int H  = 128;
static constexpr int W  = 128;
static constexpr int C  = 64;
static constexpr int NTOT = B * H * W * C;    // 16,777,216
static constexpr float DT  = 0.2f;
static constexpr float EPS = 1e-3f;

// Scratch
__device__ float d_f_buf[NTOT];               // conv1 output (f == h_init)
// fp16 weights, single plane: [conv][ty][n*200 + k], k = tx*64 + ci
__device__ __half d_wh[2][3][64 * 200];

// ===========================================================================
// PTX helpers (plain-PTX, valid on .target sm_103)
// ===========================================================================
__device__ __forceinline__ uint32_t smem_u32(const void* p) {
    uint32_t a;
    asm("{ .reg .u64 t; cvta.to.shared.u64 t, %1; cvt.u32.u64 %0, t; }"
        : "=r"(a) : "l"(p));
    return a;
}

__device__ __forceinline__ void ldsm_x4(uint32_t (&r)[4], uint32_t addr) {
    asm volatile("ldmatrix.sync.aligned.m8n8.x4.shared.b16 {%0,%1,%2,%3}, [%4];"
                 : "=r"(r[0]), "=r"(r[1]), "=r"(r[2]), "=r"(r[3]) : "r"(addr));
}

__device__ __forceinline__ void mma_f16(float (&d)[4], const uint32_t (&a)[4],
                                        uint32_t b0, uint32_t b1) {
    asm volatile(
        "mma.sync.aligned.m16n8k16.row.col.f32.f16.f16.f32 "
        "{%0,%1,%2,%3}, {%4,%5,%6,%7}, {%8,%9}, {%0,%1,%2,%3};"
        : "+f"(d[0]), "+f"(d[1]), "+f"(d[2]), "+f"(d[3])
        : "r"(a[0]), "r"(a[1]), "r"(a[2]), "r"(a[3]), "r"(b0), "r"(b1));
}

__device__ __forceinline__ void cp_async16(uint32_t saddr, const void* gaddr) {
    asm volatile("cp.async.cg.shared.global [%0], [%1], 16;"
                 :: "r"(saddr), "l"(gaddr) : "memory");
}
__device__ __forceinline__ void cp_commit() {
    asm volatile("cp.async.commit_group;" ::: "memory");
}
template <int N>
__device__ __forceinline__ void cp_wait() {
    asm volatile("cp.async.wait_group %0;" :: "n"(N) : "memory");
}

__device__ __forceinline__ uint32_t h2_bits(__half2 v) {
    uint32_t u;
    memcpy(&u, &v, 4);
    return u;
}

// ===========================================================================
// Weight prep: HWIO [3][3][64][64] -> per-ty [N=64][K=192] fp16 (single
// plane), rows padded to 200 halfs (400 B).
// ===========================================================================
__global__ void prep_weights(const float* __restrict__ fw,
                             const float* __restrict__ gw)
{
    int idx = blockIdx.x * blockDim.x + threadIdx.x;     // 2*3*192*64 = 73728
    if (idx >= 73728) return;
    int conv = idx / 36864;  int r = idx - conv * 36864;
    int ty   = r / 12288;    r -= ty * 12288;
    int k    = r >> 6;       int n = r & 63;             // k 0..191, n = cout
    int tx   = k >> 6;       int ci = k & 63;
    const float* w = conv ? gw : fw;
    float v = w[(((ty * 3 + tx) * 64) + ci) * 64 + n];
    d_wh[conv][ty][n * 200 + k] = __float2half_rn(v);
}

// ===========================================================================
// Conv v5: 2 output rows per block (M=256), mma.sync fp16 2-pass
// (A split hi/lo fp16, B single fp16 plane -> 16 mma / ks vs 24).
// Grid (64, 16); 512 threads / 16 warps as 8(m) x 2(n): warp tile m32 x n32.
// A: rows y0-1..y0+2 in 3 rotating slots (hi/lo planes).
// B: ALL 3 ty planes resident (76.8 KB), single upfront cp.async wait.
// SMEM: 3*18720*2 + 3*12800*2 = 189,120 B -> 1 CTA/SM.
// ===========================================================================
static constexpr int A_STRIDE = 72;
static constexpr int A_PLANE  = 130 * A_STRIDE;           // 9360 halfs
static constexpr int A_SLOT   = 2 * A_PLANE;              // hi+lo, 18720 halfs
static constexpr int B_PLANE  = 64 * 200;                 // 12800 halfs per ty
static constexpr int CONV_SMEM_BYTES = (3 * A_SLOT + 3 * B_PLANE) * 2;  // 189,120
static constexpr int CT = 512;

__global__ __launch_bounds__(CT, 1)
void conv_mma(const float* __restrict__ in,
              const __half* __restrict__ wbase,           // d_wh[conv]
              const float* __restrict__ gamma,
              const float* __restrict__ beta,
              const float* __restrict__ mean,
              const float* __restrict__ var,
              float* __restrict__ out)
{
    extern __shared__ __align__(16) char smem_raw[];
    __half* s_a = reinterpret_cast<__half*>(smem_raw);    // 3 slots (hi|lo)
    __half* s_b = s_a + 3 * A_SLOT;                       // 3 ty planes
    __shared__ float s_scale[64], s_shift[64];

    const int tid  = threadIdx.x;
    const int wid  = tid >> 5;
    const int lane = tid & 31;
    const int y0   = blockIdx.x * 2;
    const int b    = blockIdx.y;
    const int wm   = wid & 7;        // m32 tile over 256 px
    const int wn   = wid >> 3;       // n32 tile over 64 couts
    const int r_out = wm >> 2;       // output row within block (0/1)
    const int xw    = (wm & 3) * 32; // x offset of warp tile

    if (tid < 64) {
        float sc = gamma[tid] * rsqrtf(var[tid] + EPS);
        s_scale[tid] = sc;
        s_shift[tid] = beta[tid] - mean[tid] * sc;
    }

    const uint32_t a_base0 = smem_u32(s_a);
    const uint32_t b_base  = smem_u32(s_b);

    // ---- issue cp.async for ALL B weights (3 ty planes, 76,800 B) ----
    {
        const char* src = reinterpret_cast<const char*>(wbase);
#pragma unroll
        for (int q = 0; q < 10; ++q) {
            int idx = tid + q * CT;
            if (idx < 4800) cp_async16(b_base + idx * 16, src + idx * 16);
        }
        cp_commit();
    }

    const float* inb = in + ((size_t)b * H) * W * C;

    const int r8  = lane & 7;
    const int sel = lane >> 3;
    const int a_row_off = (sel & 1) * 8 + r8;
    const int a_kh      = (sel >> 1) * 16;
    const int b_n_off   = (sel >> 1) * 8 + r8;
    const int b_kh      = (sel & 1) * 16;

    // ---- prefetch input row y0+2 (4th row) into registers ----
    float4 pr[5];
    {
        const int yy = y0 + 2;
        const bool rowok = (unsigned)yy < (unsigned)H;
#pragma unroll
        for (int q = 0; q < 5; ++q) {
            const int e = tid + q * CT;
            pr[q] = make_float4(0.f, 0.f, 0.f, 0.f);
            if (e < 2080) {
                const int px = e >> 4;
                const int c4 = (e & 15) << 2;
                if (rowok && px >= 1 && px <= 128)
                    pr[q] = *reinterpret_cast<const float4*>(
                        inb + ((size_t)yy * W + (px - 1)) * C + c4);
            }
        }
    }
    __syncthreads();   // s_scale/s_shift ready

    // ---- stage input rows y0-1, y0, y0+1 into slots 0,1,2 ----
#pragma unroll
    for (int q = 0; q < 13; ++q) {
        const int idx = tid + q * CT;
        if (idx >= 6240) break;
        const int r  = idx / 2080;
        const int e  = idx - r * 2080;
        const int px = e >> 4;
        const int c4 = (e & 15) << 2;
        const int yy = y0 - 1 + r;
        float v0 = 0.f, v1 = 0.f, v2 = 0.f, v3 = 0.f;
        if ((unsigned)yy < (unsigned)H && px >= 1 && px <= 128) {
            float4 t = *reinterpret_cast<const float4*>(
                inb + ((size_t)yy * W + (px - 1)) * C + c4);
            v0 = fmaxf(fmaf(t.x, s_scale[c4],     s_shift[c4]),     0.f);
            v1 = fmaxf(fmaf(t.y, s_scale[c4 + 1], s_shift[c4 + 1]), 0.f);
            v2 = fmaxf(fmaf(t.z, s_scale[c4 + 2], s_shift[c4 + 2]), 0.f);
            v3 = fmaxf(fmaf(t.w, s_scale[c4 + 3], s_shift[c4 + 3]), 0.f);
        }
        __half2 h01 = __floats2half2_rn(v0, v1);
        __half2 h23 = __floats2half2_rn(v2, v3);
        __half2 l01 = __floats2half2_rn(v0 - __low2float(h01), v1 - __high2float(h01));
        __half2 l23 = __floats2half2_rn(v2 - __low2float(h23), v3 - __high2float(h23));
        __half* slot = s_a + r * A_SLOT;
        const int o = px * A_STRIDE + c4;
        *reinterpret_cast<uint2*>(slot + o)           = make_uint2(h2_bits(h01), h2_bits(h23));
        *reinterpret_cast<uint2*>(slot + A_PLANE + o) = make_uint2(h2_bits(l01), h2_bits(l23));
    }
    cp_wait<0>();      // all B planes arrived
    __syncthreads();

    float acc[2][4][4];            // [m16 half][n8 quarter]
#pragma unroll
    for (int mt = 0; mt < 2; ++mt)
#pragma unroll
        for (int nt = 0; nt < 4; ++nt)
#pragma unroll
            for (int e = 0; e < 4; ++e) acc[mt][nt][e] = 0.f;

    // ---------------- mma over 3 ty ----------------
#pragma unroll
    for (int ty = 0; ty < 3; ++ty) {
        int slot = r_out + ty;           // input row index
        if (slot >= 3) slot -= 3;        // rotating slot
        const uint32_t ah_base = a_base0 + (uint32_t)slot * (A_SLOT * 2);
        const uint32_t al_base = ah_base + A_PLANE * 2;
        const uint32_t bt_base = b_base + (uint32_t)ty * (B_PLANE * 2);

#pragma unroll
        for (int ks = 0; ks < 12; ++ks) {
            const int tx   = ks >> 2;
            const int ci16 = ks & 3;

            uint32_t afr[2][2][4];     // [m16 half][plane hi/lo]
#pragma unroll
            for (int mt = 0; mt < 2; ++mt) {
                const int px = xw + mt * 16 + a_row_off + tx;
                const uint32_t off = (uint32_t)(px * (A_STRIDE * 2) + ci16 * 32 + a_kh);
                ldsm_x4(afr[mt][0], ah_base + off);
                ldsm_x4(afr[mt][1], al_base + off);
            }
            uint32_t bfr[2][4];        // [n16 group]
#pragma unroll
            for (int g = 0; g < 2; ++g) {
                const int n = wn * 32 + g * 16 + b_n_off;
                const uint32_t off = (uint32_t)(n * 400 + tx * 128 + ci16 * 32 + b_kh);
                ldsm_x4(bfr[g], bt_base + off);
            }
#pragma unroll
            for (int mt = 0; mt < 2; ++mt)
#pragma unroll
                for (int nt = 0; nt < 4; ++nt) {
                    const int g = nt >> 1, h2 = (nt & 1) * 2;
                    mma_f16(acc[mt][nt], afr[mt][0], bfr[g][h2], bfr[g][h2 + 1]);
                    mma_f16(acc[mt][nt], afr[mt][1], bfr[g][h2], bfr[g][h2 + 1]);
                }
        }

        if (ty == 0) {
            // slot0 (row y0-1) dead -> refill with row y0+2 for ty=2.
            __syncthreads();
            const int yy = y0 + 2;
            const bool rowok = (unsigned)yy < (unsigned)H;
#pragma unroll
            for (int q = 0; q < 5; ++q) {
                const int e = tid + q * CT;
                if (e >= 2080) break;
                const int px = e >> 4;
                const int c4 = (e & 15) << 2;
                float v0 = 0.f, v1 = 0.f, v2 = 0.f, v3 = 0.f;
                if (rowok && px >= 1 && px <= 128) {
                    v0 = fmaxf(fmaf(pr[q].x, s_scale[c4],     s_shift[c4]),     0.f);
                    v1 = fmaxf(fmaf(pr[q].y, s_scale[c4 + 1], s_shift[c4 + 1]), 0.f);
                    v2 = fmaxf(fmaf(pr[q].z, s_scale[c4 + 2], s_shift[c4 + 2]), 0.f);
                    v3 = fmaxf(fmaf(pr[q].w, s_scale[c4 + 3], s_shift[c4 + 3]), 0.f);
                }
                __half2 h01 = __floats2half2_rn(v0, v1);
                __half2 h23 = __floats2half2_rn(v2, v3);
                __half2 l01 = __floats2half2_rn(v0 - __low2float(h01), v1 - __high2float(h01));
                __half2 l23 = __floats2half2_rn(v2 - __low2float(h23), v3 - __high2float(h23));
                __half* slot0 = s_a;
                const int o = px * A_STRIDE + c4;
                *reinterpret_cast<uint2*>(slot0 + o) =
                    make_uint2(h2_bits(h01), h2_bits(h23));
                *reinterpret_cast<uint2*>(slot0 + A_PLANE + o) =
                    make_uint2(h2_bits(l01), h2_bits(l23));
            }
            // ty=1 reads slot1/slot2 only -> no barrier needed here.
        } else if (ty == 1) {
            __syncthreads();   // slot0 rewrite visible before ty=2 reads it
        }
    }

    // ---- epilogue: fp32 accumulators -> NHWC output ----
    const int ygl = y0 + r_out;
    float* ob = out + (((size_t)b * H + ygl) * W) * C;
#pragma unroll
    for (int mt = 0; mt < 2; ++mt) {
        const int x0 = xw + mt * 16 + (lane >> 2);
        float* row0 = ob + (size_t)x0 * C;
        float* row1 = row0 + 8 * C;
#pragma unroll
        for (int nt = 0; nt < 4; ++nt) {
            const int co = wn * 32 + nt * 8 + (lane & 3) * 2;
            *reinterpret_cast<float2*>(row0 + co) = make_float2(acc[mt][nt][0], acc[mt][nt][1]);
            *reinterpret_cast<float2*>(row1 + co) = make_float2(acc[mt][nt][2], acc[mt][nt][3]);
        }
    }
}

// ===========================================================================
// Fused diffusion (exact R11 version): channel-pair mapping, coefficients in
// registers, Sobel rows read directly from global (L1/L2-hot).
// ===========================================================================
static constexpr int DIFF_SMEM_BYTES = 4 * 8192 * 4;   // 131,072 B

__global__ __launch_bounds__(512, 1)
void diffuse_fused(const float* __restrict__ f,
                   float* __restrict__ outh,
                   const float* __restrict__ g,
                   const float* __restrict__ gamma,
                   const float* __restrict__ beta,
                   const float* __restrict__ mean,
                   const float* __restrict__ var)
{
    extern __shared__ float sm[];
    float* P0 = sm;              // F, then h ping
    float* P1 = sm + 8192;       // G, then h pong
    float* BX = sm + 16384;      // 2*DT*Dx
    float* BY = sm + 24576;      // 2*DT*Dy
    __shared__ float sc[64], sh[64];

    const int tid = threadIdx.x;
    const int y   = blockIdx.x;
    const int b   = blockIdx.y;

    if (tid < 64) {
        float s = gamma[tid] * rsqrtf(var[tid] + EPS);
        sc[tid] = s;
        sh[tid] = beta[tid] - mean[tid] * s;
    }

    const size_t rowbase = (((size_t)b * H) + y) * W * C;
    const float* frow = f + rowbase;
    const float* grow = g + rowbase;
#pragma unroll
    for (int q = 0; q < 4; ++q) {
        const int idx = (tid + q * 512) * 4;
        *reinterpret_cast<float4*>(P0 + idx) = *reinterpret_cast<const float4*>(frow + idx);
        *reinterpret_cast<float4*>(P1 + idx) = *reinterpret_cast<const float4*>(grow + idx);
    }
    __syncthreads();

    const int c = (tid & 31) * 2;
    const float2 sc2 = make_float2(sc[c], sc[c + 1]);
    const float2 sh2 = make_float2(sh[c], sh[c + 1]);

    const int ym = (y == 0) ? 1 : y - 1;
    const int yp = (y == H - 1) ? H - 2 : y + 1;
    const float* fm = f + ((((size_t)b * H) + ym) * W) * C;
    const float* fp = f + ((((size_t)b * H) + yp) * W) * C;

    float2 hprev[8], hcur[8], E2r[8], axr[8], cdr[8], cfr[8];

#pragma unroll
    for (int j = 0; j < 8; ++j) {
        const int i = (tid + j * 512) * 2;
        const int x = i >> 6;
        const int xm = (x == 0) ? 1 : x - 1;
        const int xp = (x == W - 1) ? W - 2 : x + 1;

        const float2 f2 = *reinterpret_cast<const float2*>(P0 + i);
        const float2 g2 = *reinterpret_cast<const float2*>(P1 + i);

        const float2 am = *reinterpret_cast<const float2*>(fm + xm * 64 + c);
        const float2 a0 = *reinterpret_cast<const float2*>(fm + x  * 64 + c);
        const float2 ap = *reinterpret_cast<const float2*>(fm + xp * 64 + c);
        const float2 bm = *reinterpret_cast<const float2*>(fp + xm * 64 + c);
        const float2 b0 = *reinterpret_cast<const float2*>(fp + x  * 64 + c);
        const float2 bp = *reinterpret_cast<const float2*>(fp + xp * 64 + c);
        const float2 fxm = *reinterpret_cast<const float2*>(P0 + xm * 64 + c);
        const float2 fxp = *reinterpret_cast<const float2*>(P0 + xp * 64 + c);

        float dyx = (bm.x + 2.f * b0.x + bp.x) - (am.x + 2.f * a0.x + ap.x);
        float dyy = (bm.y + 2.f * b0.y + bp.y) - (am.y + 2.f * a0.y + ap.y);
        float dxx = (ap.x - am.x) + 2.f * (fxp.x - fxm.x) + (bp.x - bm.x);
        float dxy = (ap.y - am.y) + 2.f * (fxp.y - fxm.y) + (bp.y - bm.y);

        float bxx = (2.f * DT) / (0.25f * dyx * dyx + 1.f);
        float bxy = (2.f * DT) / (0.25f * dyy * dyy + 1.f);
        float byx = (2.f * DT) / (0.25f * dxx * dxx + 1.f);
        float byy = (2.f * DT) / (0.25f * dxy * dxy + 1.f);
        *reinterpret_cast<float2*>(BX + i) = make_float2(bxx, bxy);
        *reinterpret_cast<float2*>(BY + i) = make_float2(byx, byy);

        cdr[j] = make_float2(1.f / (1.f + bxx + byx), 1.f / (1.f + bxy + byy));
        axr[j] = make_float2(DT * g2.x, DT * g2.y);
        cfr[j] = make_float2(2.f * DT * f2.x, 2.f * DT * f2.y);
        hprev[j] = f2;
        hcur[j]  = f2;

        const int ixm = (i + 8192 - 64) & 8191;
        const int ixp = (i + 64) & 8191;
        const float2 gxm = *reinterpret_cast<const float2*>(P1 + ixm);
        const float2 gxp = *reinterpret_cast<const float2*>(P1 + ixp);
        const float gcm = P1[(i & ~63) | ((c + 63) & 63)];
        const float gcp = P1[(i & ~63) | ((c + 2) & 63)];
        E2r[j].x = DT * ((gxm.x - gxp.x) + (gcm - g2.y));
        E2r[j].y = DT * ((gxm.y - gxp.y) + (g2.x - gcp));
    }
    __syncthreads();

#pragma unroll
    for (int k = 0; k < 5; ++k) {
        float* rb = (k & 1) ? P1 : P0;
        float* wb = (k & 1) ? P0 : P1;
#pragma unroll
        for (int j = 0; j < 8; ++j) {
            const int i = (tid + j * 512) * 2;
            const int ixm = (i + 8192 - 64) & 8191;
            const int ixp = (i + 64) & 8191;
            const float2 bx2 = *reinterpret_cast<const float2*>(BX + i);
            const float2 by2 = *reinterpret_cast<const float2*>(BY + i);
            const float2 rxm = *reinterpret_cast<const float2*>(rb + ixm);
            const float2 rxp = *reinterpret_cast<const float2*>(rb + ixp);
            const float rcm = rb[(i & ~63) | ((c + 63) & 63)];
            const float rcp = rb[(i & ~63) | ((c + 2) & 63)];
            const float2 hc = hcur[j];
            const float2 ax = axr[j];

            float s0 = (1.f - bx2.x - by2.x) * hprev[j].x;
            s0 = fmaf(-E2r[j].x, hc.x, s0);
            s0 = fmaf(bx2.x, rxm.x + rxp.x, s0);
            s0 = fmaf(ax.x,  rxp.x - rxm.x, s0);
            s0 = fmaf(by2.x, rcm + hc.y, s0);
            s0 = fmaf(ax.x,  hc.y - rcm, s0);
            s0 = (s0 + cfr[j].x) * cdr[j].x;

            float s1 = (1.f - bx2.y - by2.y) * hprev[j].y;
            s1 = fmaf(-E2r[j].y, hc.y, s1);
            s1 = fmaf(bx2.y, rxm.y + rxp.y, s1);
            s1 = fmaf(ax.y,  rxp.y - rxm.y, s1);
            s1 = fmaf(by2.y, hc.x + rcp, s1);
            s1 = fmaf(ax.y,  rcp - hc.x, s1);
            s1 = (s1 + cfr[j].y) * cdr[j].y;

            hprev[j] = hc;
            hcur[j]  = make_float2(s0, s1);
            if (k < 4) *reinterpret_cast<float2*>(wb + i) = hcur[j];
        }
        if (k < 4) __syncthreads();
    }

    float* o = outh + rowbase;
#pragma unroll
    for (int j = 0; j < 8; ++j) {
        const int i = (tid + j * 512) * 2;
        float2 r = make_float2(fmaxf(fmaf(hcur[j].x, sc2.x, sh2.x), 0.f),
                               fmaxf(fmaf(hcur[j].y, sc2.y, sh2.y), 0.f));
        *reinterpret_cast<float2*>(o + i) = r;
    }
}

// ===========================================================================
extern "C" void kernel_launch(void* const* d_in, const int* in_sizes, int n_in,
                              void* d_out, int out_size)
{
    const float* x   = (const float*)d_in[0];
    const float* f_w = (const float*)d_in[1];
    const float* g_w = (const float*)d_in[2];
    const float* bnf_gamma = (const float*)d_in[3];
    const float* bnf_beta  = (const float*)d_in[4];
    const float* bnf_mean  = (const float*)d_in[5];
    const float* bnf_var   = (const float*)d_in[6];
    const float* bng_gamma = (const float*)d_in[7];
    const float* bng_beta  = (const float*)d_in[8];
    const float* bng_mean  = (const float*)d_in[9];
    const float* bng_var   = (const float*)d_in[10];
    const float* bno_gamma = (const float*)d_in[11];
    const float* bno_beta  = (const float*)d_in[12];
    const float* bno_mean  = (const float*)d_in[13];
    const float* bno_var   = (const float*)d_in[14];

    float* out = (float*)d_out;            // [0:N) = h, [N:2N) = g

    float* fptr = nullptr;
    cudaGetSymbolAddress((void**)&fptr, d_f_buf);
    __half* wptr = nullptr;
    cudaGetSymbolAddress((void**)&wptr, d_wh);

    cudaFuncSetAttribute(conv_mma,
                         cudaFuncAttributeMaxDynamicSharedMemorySize, CONV_SMEM_BYTES);
    cudaFuncSetAttribute(diffuse_fused,
                         cudaFuncAttributeMaxDynamicSharedMemorySize, DIFF_SMEM_BYTES);

    // 1) weight transform (both convs)
    prep_weights<<<288, 256>>>(f_w, g_w);

    dim3 cgrid(H / 2, B);

    // 2) f = conv(relu(bn_f(x)), f_w)
    conv_mma<<<cgrid, CT, CONV_SMEM_BYTES>>>(
        x, wptr, bnf_gamma, bnf_beta, bnf_mean, bnf_var, fptr);

    // 3) g = conv(relu(bn_g(f)), g_w) -> d_out[N:2N)
    conv_mma<<<cgrid, CT, CONV_SMEM_BYTES>>>(
        fptr, wptr + 3 * B_PLANE, bng_gamma, bng_beta, bng_mean, bng_var, out + NTOT);

    // 4) fused sobel + coefficients + 5 diffusion iters + bn_o/relu -> d_out[0:N)
    dim3 dgrid(H, B);
    diffuse_fused<<<dgrid, 512, DIFF_SMEM_BYTES>>>(
        fptr, out, out + NTOT, bno_gamma, bno_beta, bno_mean, bno_var);
}

// round 14
// speedup vs baseline: 1.2534x; 1.0429x over previous
#include <cuda_runtime.h>
#include <cuda_fp16.h>
#include <cstdint>

// ===========================================================================
// Problem constants
// ===========================================================================
static constexpr int B  = 16;
static constexpr int H  = 128;
static constexpr int W  = 128;
static constexpr int C  = 64;
static constexpr int NTOT = B * H * W * C;    // 16,777,216
static constexpr float DT  = 0.2f;
static constexpr float EPS = 1e-3f;

// Scratch
__device__ float d_f_buf[NTOT];               // conv1 output (f == h_init)
// fp16 weights, single plane: [conv][ty][n*200 + k], k = tx*64 + ci
__device__ __half d_wh[2][3][64 * 200];

// ===========================================================================
// PTX helpers (plain-PTX, valid on .target sm_103)
// ===========================================================================
__device__ __forceinline__ uint32_t smem_u32(const void* p) {
    uint32_t a;
    asm("{ .reg .u64 t; cvta.to.shared.u64 t, %1; cvt.u32.u64 %0, t; }"
        : "=r"(a) : "l"(p));
    return a;
}

__device__ __forceinline__ void ldsm_x4(uint32_t (&r)[4], uint32_t addr) {
    asm volatile("ldmatrix.sync.aligned.m8n8.x4.shared.b16 {%0,%1,%2,%3}, [%4];"
                 : "=r"(r[0]), "=r"(r[1]), "=r"(r[2]), "=r"(r[3]) : "r"(addr));
}

__device__ __forceinline__ void mma_f16(float (&d)[4], const uint32_t (&a)[4],
                                        uint32_t b0, uint32_t b1) {
    asm volatile(
        "mma.sync.aligned.m16n8k16.row.col.f32.f16.f16.f32 "
        "{%0,%1,%2,%3}, {%4,%5,%6,%7}, {%8,%9}, {%0,%1,%2,%3};"
        : "+f"(d[0]), "+f"(d[1]), "+f"(d[2]), "+f"(d[3])
        : "r"(a[0]), "r"(a[1]), "r"(a[2]), "r"(a[3]), "r"(b0), "r"(b1));
}

__device__ __forceinline__ void cp_async16(uint32_t saddr, const void* gaddr) {
    asm volatile("cp.async.cg.shared.global [%0], [%1], 16;"
                 :: "r"(saddr), "l"(gaddr) : "memory");
}
__device__ __forceinline__ void cp_commit() {
    asm volatile("cp.async.commit_group;" ::: "memory");
}
template <int N>
__device__ __forceinline__ void cp_wait() {
    asm volatile("cp.async.wait_group %0;" :: "n"(N) : "memory");
}

__device__ __forceinline__ uint32_t h2_bits(__half2 v) {
    uint32_t u;
    memcpy(&u, &v, 4);
    return u;
}

// ===========================================================================
// Weight prep: HWIO [3][3][64][64] -> per-ty [N=64][K=192] fp16 (single
// plane), rows padded to 200 halfs (400 B).
// ===========================================================================
__global__ void prep_weights(const float* __restrict__ fw,
                             const float* __restrict__ gw)
{
    int idx = blockIdx.x * blockDim.x + threadIdx.x;     // 2*3*192*64 = 73728
    if (idx >= 73728) return;
    int conv = idx / 36864;  int r = idx - conv * 36864;
    int ty   = r / 12288;    r -= ty * 12288;
    int k    = r >> 6;       int n = r & 63;             // k 0..191, n = cout
    int tx   = k >> 6;       int ci = k & 63;
    const float* w = conv ? gw : fw;
    float v = w[(((ty * 3 + tx) * 64) + ci) * 64 + n];
    d_wh[conv][ty][n * 200 + k] = __float2half_rn(v);
}

// ===========================================================================
// Conv v5 (unchanged from R13): 2 output rows per block (M=256), mma.sync
// fp16 2-pass (A split hi/lo fp16, B single fp16 plane).
// ===========================================================================
static constexpr int A_STRIDE = 72;
static constexpr int A_PLANE  = 130 * A_STRIDE;           // 9360 halfs
static constexpr int A_SLOT   = 2 * A_PLANE;              // hi+lo, 18720 halfs
static constexpr int B_PLANE  = 64 * 200;                 // 12800 halfs per ty
static constexpr int CONV_SMEM_BYTES = (3 * A_SLOT + 3 * B_PLANE) * 2;  // 189,120
static constexpr int CT = 512;

__global__ __launch_bounds__(CT, 1)
void conv_mma(const float* __restrict__ in,
              const __half* __restrict__ wbase,           // d_wh[conv]
              const float* __restrict__ gamma,
              const float* __restrict__ beta,
              const float* __restrict__ mean,
              const float* __restrict__ var,
              float* __restrict__ out)
{
    extern __shared__ __align__(16) char smem_raw[];
    __half* s_a = reinterpret_cast<__half*>(smem_raw);    // 3 slots (hi|lo)
    __half* s_b = s_a + 3 * A_SLOT;                       // 3 ty planes
    __shared__ float s_scale[64], s_shift[64];

    const int tid  = threadIdx.x;
    const int wid  = tid >> 5;
    const int lane = tid & 31;
    const int y0   = blockIdx.x * 2;
    const int b    = blockIdx.y;
    const int wm   = wid & 7;        // m32 tile over 256 px
    const int wn   = wid >> 3;       // n32 tile over 64 couts
    const int r_out = wm >> 2;       // output row within block (0/1)
    const int xw    = (wm & 3) * 32; // x offset of warp tile

    if (tid < 64) {
        float sc = gamma[tid] * rsqrtf(var[tid] + EPS);
        s_scale[tid] = sc;
        s_shift[tid] = beta[tid] - mean[tid] * sc;
    }

    const uint32_t a_base0 = smem_u32(s_a);
    const uint32_t b_base  = smem_u32(s_b);

    // ---- issue cp.async for ALL B weights (3 ty planes, 76,800 B) ----
    {
        const char* src = reinterpret_cast<const char*>(wbase);
#pragma unroll
        for (int q = 0; q < 10; ++q) {
            int idx = tid + q * CT;
            if (idx < 4800) cp_async16(b_base + idx * 16, src + idx * 16);
        }
        cp_commit();
    }

    const float* inb = in + ((size_t)b * H) * W * C;

    const int r8  = lane & 7;
    const int sel = lane >> 3;
    const int a_row_off = (sel & 1) * 8 + r8;
    const int a_kh      = (sel >> 1) * 16;
    const int b_n_off   = (sel >> 1) * 8 + r8;
    const int b_kh      = (sel & 1) * 16;

    // ---- prefetch input row y0+2 (4th row) into registers ----
    float4 pr[5];
    {
        const int yy = y0 + 2;
        const bool rowok = (unsigned)yy < (unsigned)H;
#pragma unroll
        for (int q = 0; q < 5; ++q) {
            const int e = tid + q * CT;
            pr[q] = make_float4(0.f, 0.f, 0.f, 0.f);
            if (e < 2080) {
                const int px = e >> 4;
                const int c4 = (e & 15) << 2;
                if (rowok && px >= 1 && px <= 128)
                    pr[q] = *reinterpret_cast<const float4*>(
                        inb + ((size_t)yy * W + (px - 1)) * C + c4);
            }
        }
    }
    __syncthreads();   // s_scale/s_shift ready

    // ---- stage input rows y0-1, y0, y0+1 into slots 0,1,2 ----
#pragma unroll
    for (int q = 0; q < 13; ++q) {
        const int idx = tid + q * CT;
        if (idx >= 6240) break;
        const int r  = idx / 2080;
        const int e  = idx - r * 2080;
        const int px = e >> 4;
        const int c4 = (e & 15) << 2;
        const int yy = y0 - 1 + r;
        float v0 = 0.f, v1 = 0.f, v2 = 0.f, v3 = 0.f;
        if ((unsigned)yy < (unsigned)H && px >= 1 && px <= 128) {
            float4 t = *reinterpret_cast<const float4*>(
                inb + ((size_t)yy * W + (px - 1)) * C + c4);
            v0 = fmaxf(fmaf(t.x, s_scale[c4],     s_shift[c4]),     0.f);
            v1 = fmaxf(fmaf(t.y, s_scale[c4 + 1], s_shift[c4 + 1]), 0.f);
            v2 = fmaxf(fmaf(t.z, s_scale[c4 + 2], s_shift[c4 + 2]), 0.f);
            v3 = fmaxf(fmaf(t.w, s_scale[c4 + 3], s_shift[c4 + 3]), 0.f);
        }
        __half2 h01 = __floats2half2_rn(v0, v1);
        __half2 h23 = __floats2half2_rn(v2, v3);
        __half2 l01 = __floats2half2_rn(v0 - __low2float(h01), v1 - __high2float(h01));
        __half2 l23 = __floats2half2_rn(v2 - __low2float(h23), v3 - __high2float(h23));
        __half* slot = s_a + r * A_SLOT;
        const int o = px * A_STRIDE + c4;
        *reinterpret_cast<uint2*>(slot + o)           = make_uint2(h2_bits(h01), h2_bits(h23));
        *reinterpret_cast<uint2*>(slot + A_PLANE + o) = make_uint2(h2_bits(l01), h2_bits(l23));
    }
    cp_wait<0>();      // all B planes arrived
    __syncthreads();

    float acc[2][4][4];            // [m16 half][n8 quarter]
#pragma unroll
    for (int mt = 0; mt < 2; ++mt)
#pragma unroll
        for (int nt = 0; nt < 4; ++nt)
#pragma unroll
            for (int e = 0; e < 4; ++e) acc[mt][nt][e] = 0.f;

    // ---------------- mma over 3 ty ----------------
#pragma unroll
    for (int ty = 0; ty < 3; ++ty) {
        int slot = r_out + ty;           // input row index
        if (slot >= 3) slot -= 3;        // rotating slot
        const uint32_t ah_base = a_base0 + (uint32_t)slot * (A_SLOT * 2);
        const uint32_t al_base = ah_base + A_PLANE * 2;
        const uint32_t bt_base = b_base + (uint32_t)ty * (B_PLANE * 2);

#pragma unroll
        for (int ks = 0; ks < 12; ++ks) {
            const int tx   = ks >> 2;
            const int ci16 = ks & 3;

            uint32_t afr[2][2][4];     // [m16 half][plane hi/lo]
#pragma unroll
            for (int mt = 0; mt < 2; ++mt) {
                const int px = xw + mt * 16 + a_row_off + tx;
                const uint32_t off = (uint32_t)(px * (A_STRIDE * 2) + ci16 * 32 + a_kh);
                ldsm_x4(afr[mt][0], ah_base + off);
                ldsm_x4(afr[mt][1], al_base + off);
            }
            uint32_t bfr[2][4];        // [n16 group]
#pragma unroll
            for (int g = 0; g < 2; ++g) {
                const int n = wn * 32 + g * 16 + b_n_off;
                const uint32_t off = (uint32_t)(n * 400 + tx * 128 + ci16 * 32 + b_kh);
                ldsm_x4(bfr[g], bt_base + off);
            }
#pragma unroll
            for (int mt = 0; mt < 2; ++mt)
#pragma unroll
                for (int nt = 0; nt < 4; ++nt) {
                    const int g = nt >> 1, h2 = (nt & 1) * 2;
                    mma_f16(acc[mt][nt], afr[mt][0], bfr[g][h2], bfr[g][h2 + 1]);
                    mma_f16(acc[mt][nt], afr[mt][1], bfr[g][h2], bfr[g][h2 + 1]);
                }
        }

        if (ty == 0) {
            // slot0 (row y0-1) dead -> refill with row y0+2 for ty=2.
            __syncthreads();
            const int yy = y0 + 2;
            const bool rowok = (unsigned)yy < (unsigned)H;
#pragma unroll
            for (int q = 0; q < 5; ++q) {
                const int e = tid + q * CT;
                if (e >= 2080) break;
                const int px = e >> 4;
                const int c4 = (e & 15) << 2;
                float v0 = 0.f, v1 = 0.f, v2 = 0.f, v3 = 0.f;
                if (rowok && px >= 1 && px <= 128) {
                    v0 = fmaxf(fmaf(pr[q].x, s_scale[c4],     s_shift[c4]),     0.f);
                    v1 = fmaxf(fmaf(pr[q].y, s_scale[c4 + 1], s_shift[c4 + 1]), 0.f);
                    v2 = fmaxf(fmaf(pr[q].z, s_scale[c4 + 2], s_shift[c4 + 2]), 0.f);
                    v3 = fmaxf(fmaf(pr[q].w, s_scale[c4 + 3], s_shift[c4 + 3]), 0.f);
                }
                __half2 h01 = __floats2half2_rn(v0, v1);
                __half2 h23 = __floats2half2_rn(v2, v3);
                __half2 l01 = __floats2half2_rn(v0 - __low2float(h01), v1 - __high2float(h01));
                __half2 l23 = __floats2half2_rn(v2 - __low2float(h23), v3 - __high2float(h23));
                __half* slot0 = s_a;
                const int o = px * A_STRIDE + c4;
                *reinterpret_cast<uint2*>(slot0 + o) =
                    make_uint2(h2_bits(h01), h2_bits(h23));
                *reinterpret_cast<uint2*>(slot0 + A_PLANE + o) =
                    make_uint2(h2_bits(l01), h2_bits(l23));
            }
            // ty=1 reads slot1/slot2 only -> no barrier needed here.
        } else if (ty == 1) {
            __syncthreads();   // slot0 rewrite visible before ty=2 reads it
        }
    }

    // ---- epilogue: fp32 accumulators -> NHWC output ----
    const int ygl = y0 + r_out;
    float* ob = out + (((size_t)b * H + ygl) * W) * C;
#pragma unroll
    for (int mt = 0; mt < 2; ++mt) {
        const int x0 = xw + mt * 16 + (lane >> 2);
        float* row0 = ob + (size_t)x0 * C;
        float* row1 = row0 + 8 * C;
#pragma unroll
        for (int nt = 0; nt < 4; ++nt) {
            const int co = wn * 32 + nt * 8 + (lane & 3) * 2;
            *reinterpret_cast<float2*>(row0 + co) = make_float2(acc[mt][nt][0], acc[mt][nt][1]);
            *reinterpret_cast<float2*>(row1 + co) = make_float2(acc[mt][nt][2], acc[mt][nt][3]);
        }
    }
}

// ===========================================================================
// Fused diffusion v4: 1024 threads, 4 float2 pairs per thread.
// Halves per-thread register state (6 arrays x 4 x 2 = 48 persistent regs)
// -> 32 warps/SM (was 16) for latency hiding. Same math as R11/R13.
// SMEM: P0, P1, BX, BY = 131,072 B -> 1 CTA/SM.
// ===========================================================================
static constexpr int DIFF_SMEM_BYTES = 4 * 8192 * 4;   // 131,072 B
static constexpr int DTH = 1024;                        // diffuse threads

__global__ __launch_bounds__(DTH, 1)
void diffuse_fused(const float* __restrict__ f,
                   float* __restrict__ outh,
                   const float* __restrict__ g,
                   const float* __restrict__ gamma,
                   const float* __restrict__ beta,
                   const float* __restrict__ mean,
                   const float* __restrict__ var)
{
    extern __shared__ float sm[];
    float* P0 = sm;              // F, then h ping
    float* P1 = sm + 8192;       // G, then h pong
    float* BX = sm + 16384;      // 2*DT*Dx
    float* BY = sm + 24576;      // 2*DT*Dy
    __shared__ float sc[64], sh[64];

    const int tid = threadIdx.x;
    const int y   = blockIdx.x;
    const int b   = blockIdx.y;

    if (tid < 64) {
        float s = gamma[tid] * rsqrtf(var[tid] + EPS);
        sc[tid] = s;
        sh[tid] = beta[tid] - mean[tid] * s;
    }

    const size_t rowbase = (((size_t)b * H) + y) * W * C;
    const float* frow = f + rowbase;
    const float* grow = g + rowbase;
#pragma unroll
    for (int q = 0; q < 2; ++q) {
        const int idx = (tid + q * DTH) * 4;
        *reinterpret_cast<float4*>(P0 + idx) = *reinterpret_cast<const float4*>(frow + idx);
        *reinterpret_cast<float4*>(P1 + idx) = *reinterpret_cast<const float4*>(grow + idx);
    }
    __syncthreads();

    const int c = (tid & 31) * 2;
    const float2 sc2 = make_float2(sc[c], sc[c + 1]);
    const float2 sh2 = make_float2(sh[c], sh[c + 1]);

    const int ym = (y == 0) ? 1 : y - 1;
    const int yp = (y == H - 1) ? H - 2 : y + 1;
    const float* fm = f + ((((size_t)b * H) + ym) * W) * C;
    const float* fp = f + ((((size_t)b * H) + yp) * W) * C;

    float2 hprev[4], hcur[4], E2r[4], axr[4], cdr[4], cfr[4];

#pragma unroll
    for (int j = 0; j < 4; ++j) {
        const int i = (tid + j * DTH) * 2;
        const int x = i >> 6;
        const int xm = (x == 0) ? 1 : x - 1;
        const int xp = (x == W - 1) ? W - 2 : x + 1;

        const float2 f2 = *reinterpret_cast<const float2*>(P0 + i);
        const float2 g2 = *reinterpret_cast<const float2*>(P1 + i);

        const float2 am = *reinterpret_cast<const float2*>(fm + xm * 64 + c);
        const float2 a0 = *reinterpret_cast<const float2*>(fm + x  * 64 + c);
        const float2 ap = *reinterpret_cast<const float2*>(fm + xp * 64 + c);
        const float2 bm = *reinterpret_cast<const float2*>(fp + xm * 64 + c);
        const float2 b0 = *reinterpret_cast<const float2*>(fp + x  * 64 + c);
        const float2 bp = *reinterpret_cast<const float2*>(fp + xp * 64 + c);
        const float2 fxm = *reinterpret_cast<const float2*>(P0 + xm * 64 + c);
        const float2 fxp = *reinterpret_cast<const float2*>(P0 + xp * 64 + c);

        float dyx = (bm.x + 2.f * b0.x + bp.x) - (am.x + 2.f * a0.x + ap.x);
        float dyy = (bm.y + 2.f * b0.y + bp.y) - (am.y + 2.f * a0.y + ap.y);
        float dxx = (ap.x - am.x) + 2.f * (fxp.x - fxm.x) + (bp.x - bm.x);
        float dxy = (ap.y - am.y) + 2.f * (fxp.y - fxm.y) + (bp.y - bm.y);

        float bxx = (2.f * DT) / (0.25f * dyx * dyx + 1.f);
        float bxy = (2.f * DT) / (0.25f * dyy * dyy + 1.f);
        float byx = (2.f * DT) / (0.25f * dxx * dxx + 1.f);
        float byy = (2.f * DT) / (0.25f * dxy * dxy + 1.f);
        *reinterpret_cast<float2*>(BX + i) = make_float2(bxx, bxy);
        *reinterpret_cast<float2*>(BY + i) = make_float2(byx, byy);

        cdr[j] = make_float2(1.f / (1.f + bxx + byx), 1.f / (1.f + bxy + byy));
        axr[j] = make_float2(DT * g2.x, DT * g2.y);
        cfr[j] = make_float2(2.f * DT * f2.x, 2.f * DT * f2.y);
        hprev[j] = f2;
        hcur[j]  = f2;

        const int ixm = (i + 8192 - 64) & 8191;
        const int ixp = (i + 64) & 8191;
        const float2 gxm = *reinterpret_cast<const float2*>(P1 + ixm);
        const float2 gxp = *reinterpret_cast<const float2*>(P1 + ixp);
        const float gcm = P1[(i & ~63) | ((c + 63) & 63)];
        const float gcp = P1[(i & ~63) | ((c + 2) & 63)];
        E2r[j].x = DT * ((gxm.x - gxp.x) + (gcm - g2.y));
        E2r[j].y = DT * ((gxm.y - gxp.y) + (g2.x - gcp));
    }
    __syncthreads();

#pragma unroll
    for (int k = 0; k < 5; ++k) {
        float* rb = (k & 1) ? P1 : P0;
        float* wb = (k & 1) ? P0 : P1;
#pragma unroll
        for (int j = 0; j < 4; ++j) {
            const int i = (tid + j * DTH) * 2;
            const int ixm = (i + 8192 - 64) & 8191;
            const int ixp = (i + 64) & 8191;
            const float2 bx2 = *reinterpret_cast<const float2*>(BX + i);
            const float2 by2 = *reinterpret_cast<const float2*>(BY + i);
            const float2 rxm = *reinterpret_cast<const float2*>(rb + ixm);
            const float2 rxp = *reinterpret_cast<const float2*>(rb + ixp);
            const float rcm = rb[(i & ~63) | ((c + 63) & 63)];
            const float rcp = rb[(i & ~63) | ((c + 2) & 63)];
            const float2 hc = hcur[j];
            const float2 ax = axr[j];

            float s0 = (1.f - bx2.x - by2.x) * hprev[j].x;
            s0 = fmaf(-E2r[j].x, hc.x, s0);
            s0 = fmaf(bx2.x, rxm.x + rxp.x, s0);
            s0 = fmaf(ax.x,  rxp.x - rxm.x, s0);
            s0 = fmaf(by2.x, rcm + hc.y, s0);
            s0 = fmaf(ax.x,  hc.y - rcm, s0);
            s0 = (s0 + cfr[j].x) * cdr[j].x;

            float s1 = (1.f - bx2.y - by2.y) * hprev[j].y;
            s1 = fmaf(-E2r[j].y, hc.y, s1);
            s1 = fmaf(bx2.y, rxm.y + rxp.y, s1);
            s1 = fmaf(ax.y,  rxp.y - rxm.y, s1);
            s1 = fmaf(by2.y, hc.x + rcp, s1);
            s1 = fmaf(ax.y,  rcp - hc.x, s1);
            s1 = (s1 + cfr[j].y) * cdr[j].y;

            hprev[j] = hc;
            hcur[j]  = make_float2(s0, s1);
            if (k < 4) *reinterpret_cast<float2*>(wb + i) = hcur[j];
        }
        if (k < 4) __syncthreads();
    }

    float* o = outh + rowbase;
#pragma unroll
    for (int j = 0; j < 4; ++j) {
        const int i = (tid + j * DTH) * 2;
        float2 r = make_float2(fmaxf(fmaf(hcur[j].x, sc2.x, sh2.x), 0.f),
                               fmaxf(fmaf(hcur[j].y, sc2.y, sh2.y), 0.f));
        *reinterpret_cast<float2*>(o + i) = r;
    }
}

// ===========================================================================
extern "C" void kernel_launch(void* const* d_in, const int* in_sizes, int n_in,
                              void* d_out, int out_size)
{
    const float* x   = (const float*)d_in[0];
    const float* f_w = (const float*)d_in[1];
    const float* g_w = (const float*)d_in[2];
    const float* bnf_gamma = (const float*)d_in[3];
    const float* bnf_beta  = (const float*)d_in[4];
    const float* bnf_mean  = (const float*)d_in[5];
    const float* bnf_var   = (const float*)d_in[6];
    const float* bng_gamma = (const float*)d_in[7];
    const float* bng_beta  = (const float*)d_in[8];
    const float* bng_mean  = (const float*)d_in[9];
    const float* bng_var   = (const float*)d_in[10];
    const float* bno_gamma = (const float*)d_in[11];
    const float* bno_beta  = (const float*)d_in[12];
    const float* bno_mean  = (const float*)d_in[13];
    const float* bno_var   = (const float*)d_in[14];

    float* out = (float*)d_out;            // [0:N) = h, [N:2N) = g

    float* fptr = nullptr;
    cudaGetSymbolAddress((void**)&fptr, d_f_buf);
    __half* wptr = nullptr;
    cudaGetSymbolAddress((void**)&wptr, d_wh);

    cudaFuncSetAttribute(conv_mma,
                         cudaFuncAttributeMaxDynamicSharedMemorySize, CONV_SMEM_BYTES);
    cudaFuncSetAttribute(diffuse_fused,
                         cudaFuncAttributeMaxDynamicSharedMemorySize, DIFF_SMEM_BYTES);

    // 1) weight transform (both convs)
    prep_weights<<<288, 256>>>(f_w, g_w);

    dim3 cgrid(H / 2, B);

    // 2) f = conv(relu(bn_f(x)), f_w)
    conv_mma<<<cgrid, CT, CONV_SMEM_BYTES>>>(
        x, wptr, bnf_gamma, bnf_beta, bnf_mean, bnf_var, fptr);

    // 3) g = conv(relu(bn_g(f)), g_w) -> d_out[N:2N)
    conv_mma<<<cgrid, CT, CONV_SMEM_BYTES>>>(
        fptr, wptr + 3 * B_PLANE, bng_gamma, bng_beta, bng_mean, bng_var, out + NTOT);

    // 4) fused sobel + coefficients + 5 diffusion iters + bn_o/relu -> d_out[0:N)
    dim3 dgrid(H, B);
    diffuse_fused<<<dgrid, DTH, DIFF_SMEM_BYTES>>>(
        fptr, out, out + NTOT, bno_gamma, bno_beta, bno_mean, bno_var);
}

// round 15
// speedup vs baseline: 1.3310x; 1.0619x over previous
#include <cuda_runtime.h>
#include <cuda_fp16.h>
#include <cstdint>

// ===========================================================================
// Problem constants
// ===========================================================================
static constexpr int B  = 16;
static constexpr int H  = 128;
static constexpr int W  = 128;
static constexpr int C  = 64;
static constexpr int NTOT = B * H * W * C;    // 16,777,216
static constexpr float DT  = 0.2f;
static constexpr float EPS = 1e-3f;

// Scratch
__device__ float d_f_buf[NTOT];               // conv1 output (f == h_init)
// fp16 weights, single plane: [conv][ty][n*200 + k], k = tx*64 + ci
__device__ __half d_wh[2][3][64 * 200];

// ===========================================================================
// PTX helpers (plain-PTX, valid on .target sm_103)
// ===========================================================================
__device__ __forceinline__ uint32_t smem_u32(const void* p) {
    uint32_t a;
    asm("{ .reg .u64 t; cvta.to.shared.u64 t, %1; cvt.u32.u64 %0, t; }"
        : "=r"(a) : "l"(p));
    return a;
}

__device__ __forceinline__ void ldsm_x4(uint32_t (&r)[4], uint32_t addr) {
    asm volatile("ldmatrix.sync.aligned.m8n8.x4.shared.b16 {%0,%1,%2,%3}, [%4];"
                 : "=r"(r[0]), "=r"(r[1]), "=r"(r[2]), "=r"(r[3]) : "r"(addr));
}

__device__ __forceinline__ void mma_f16(float (&d)[4], const uint32_t (&a)[4],
                                        uint32_t b0, uint32_t b1) {
    asm volatile(
        "mma.sync.aligned.m16n8k16.row.col.f32.f16.f16.f32 "
        "{%0,%1,%2,%3}, {%4,%5,%6,%7}, {%8,%9}, {%0,%1,%2,%3};"
        : "+f"(d[0]), "+f"(d[1]), "+f"(d[2]), "+f"(d[3])
        : "r"(a[0]), "r"(a[1]), "r"(a[2]), "r"(a[3]), "r"(b0), "r"(b1));
}

__device__ __forceinline__ void cp_async16(uint32_t saddr, const void* gaddr) {
    asm volatile("cp.async.cg.shared.global [%0], [%1], 16;"
                 :: "r"(saddr), "l"(gaddr) : "memory");
}
__device__ __forceinline__ void cp_commit() {
    asm volatile("cp.async.commit_group;" ::: "memory");
}
template <int N>
__device__ __forceinline__ void cp_wait() {
    asm volatile("cp.async.wait_group %0;" :: "n"(N) : "memory");
}

__device__ __forceinline__ uint32_t h2_bits(__half2 v) {
    uint32_t u;
    memcpy(&u, &v, 4);
    return u;
}

// ===========================================================================
// Weight prep: HWIO [3][3][64][64] -> per-ty [N=64][K=192] fp16 (single
// plane), rows padded to 200 halfs (400 B).
// ===========================================================================
__global__ void prep_weights(const float* __restrict__ fw,
                             const float* __restrict__ gw)
{
    int idx = blockIdx.x * blockDim.x + threadIdx.x;     // 2*3*192*64 = 73728
    if (idx >= 73728) return;
    int conv = idx / 36864;  int r = idx - conv * 36864;
    int ty   = r / 12288;    r -= ty * 12288;
    int k    = r >> 6;       int n = r & 63;             // k 0..191, n = cout
    int tx   = k >> 6;       int ci = k & 63;
    const float* w = conv ? gw : fw;
    float v = w[(((ty * 3 + tx) * 64) + ci) * 64 + n];
    d_wh[conv][ty][n * 200 + k] = __float2half_rn(v);
}

// ===========================================================================
// Conv v5 (unchanged from R13/R14): 2 output rows per block (M=256),
// mma.sync fp16 2-pass (A split hi/lo fp16, B single fp16 plane).
// ===========================================================================
static constexpr int A_STRIDE = 72;
static constexpr int A_PLANE  = 130 * A_STRIDE;           // 9360 halfs
static constexpr int A_SLOT   = 2 * A_PLANE;              // hi+lo, 18720 halfs
static constexpr int B_PLANE  = 64 * 200;                 // 12800 halfs per ty
static constexpr int CONV_SMEM_BYTES = (3 * A_SLOT + 3 * B_PLANE) * 2;  // 189,120
static constexpr int CT = 512;

__global__ __launch_bounds__(CT, 1)
void conv_mma(const float* __restrict__ in,
              const __half* __restrict__ wbase,           // d_wh[conv]
              const float* __restrict__ gamma,
              const float* __restrict__ beta,
              const float* __restrict__ mean,
              const float* __restrict__ var,
              float* __restrict__ out)
{
    extern __shared__ __align__(16) char smem_raw[];
    __half* s_a = reinterpret_cast<__half*>(smem_raw);    // 3 slots (hi|lo)
    __half* s_b = s_a + 3 * A_SLOT;                       // 3 ty planes
    __shared__ float s_scale[64], s_shift[64];

    const int tid  = threadIdx.x;
    const int wid  = tid >> 5;
    const int lane = tid & 31;
    const int y0   = blockIdx.x * 2;
    const int b    = blockIdx.y;
    const int wm   = wid & 7;        // m32 tile over 256 px
    const int wn   = wid >> 3;       // n32 tile over 64 couts
    const int r_out = wm >> 2;       // output row within block (0/1)
    const int xw    = (wm & 3) * 32; // x offset of warp tile

    if (tid < 64) {
        float sc = gamma[tid] * rsqrtf(var[tid] + EPS);
        s_scale[tid] = sc;
        s_shift[tid] = beta[tid] - mean[tid] * sc;
    }

    const uint32_t a_base0 = smem_u32(s_a);
    const uint32_t b_base  = smem_u32(s_b);

    // ---- issue cp.async for ALL B weights (3 ty planes, 76,800 B) ----
    {
        const char* src = reinterpret_cast<const char*>(wbase);
#pragma unroll
        for (int q = 0; q < 10; ++q) {
            int idx = tid + q * CT;
            if (idx < 4800) cp_async16(b_base + idx * 16, src + idx * 16);
        }
        cp_commit();
    }

    const float* inb = in + ((size_t)b * H) * W * C;

    const int r8  = lane & 7;
    const int sel = lane >> 3;
    const int a_row_off = (sel & 1) * 8 + r8;
    const int a_kh      = (sel >> 1) * 16;
    const int b_n_off   = (sel >> 1) * 8 + r8;
    const int b_kh      = (sel & 1) * 16;

    // ---- prefetch input row y0+2 (4th row) into registers ----
    float4 pr[5];
    {
        const int yy = y0 + 2;
        const bool rowok = (unsigned)yy < (unsigned)H;
#pragma unroll
        for (int q = 0; q < 5; ++q) {
            const int e = tid + q * CT;
            pr[q] = make_float4(0.f, 0.f, 0.f, 0.f);
            if (e < 2080) {
                const int px = e >> 4;
                const int c4 = (e & 15) << 2;
                if (rowok && px >= 1 && px <= 128)
                    pr[q] = *reinterpret_cast<const float4*>(
                        inb + ((size_t)yy * W + (px - 1)) * C + c4);
            }
        }
    }
    __syncthreads();   // s_scale/s_shift ready

    // ---- stage input rows y0-1, y0, y0+1 into slots 0,1,2 ----
#pragma unroll
    for (int q = 0; q < 13; ++q) {
        const int idx = tid + q * CT;
        if (idx >= 6240) break;
        const int r  = idx / 2080;
        const int e  = idx - r * 2080;
        const int px = e >> 4;
        const int c4 = (e & 15) << 2;
        const int yy = y0 - 1 + r;
        float v0 = 0.f, v1 = 0.f, v2 = 0.f, v3 = 0.f;
        if ((unsigned)yy < (unsigned)H && px >= 1 && px <= 128) {
            float4 t = *reinterpret_cast<const float4*>(
                inb + ((size_t)yy * W + (px - 1)) * C + c4);
            v0 = fmaxf(fmaf(t.x, s_scale[c4],     s_shift[c4]),     0.f);
            v1 = fmaxf(fmaf(t.y, s_scale[c4 + 1], s_shift[c4 + 1]), 0.f);
            v2 = fmaxf(fmaf(t.z, s_scale[c4 + 2], s_shift[c4 + 2]), 0.f);
            v3 = fmaxf(fmaf(t.w, s_scale[c4 + 3], s_shift[c4 + 3]), 0.f);
        }
        __half2 h01 = __floats2half2_rn(v0, v1);
        __half2 h23 = __floats2half2_rn(v2, v3);
        __half2 l01 = __floats2half2_rn(v0 - __low2float(h01), v1 - __high2float(h01));
        __half2 l23 = __floats2half2_rn(v2 - __low2float(h23), v3 - __high2float(h23));
        __half* slot = s_a + r * A_SLOT;
        const int o = px * A_STRIDE + c4;
        *reinterpret_cast<uint2*>(slot + o)           = make_uint2(h2_bits(h01), h2_bits(h23));
        *reinterpret_cast<uint2*>(slot + A_PLANE + o) = make_uint2(h2_bits(l01), h2_bits(l23));
    }
    cp_wait<0>();      // all B planes arrived
    __syncthreads();

    float acc[2][4][4];            // [m16 half][n8 quarter]
#pragma unroll
    for (int mt = 0; mt < 2; ++mt)
#pragma unroll
        for (int nt = 0; nt < 4; ++nt)
#pragma unroll
            for (int e = 0; e < 4; ++e) acc[mt][nt][e] = 0.f;

    // ---------------- mma over 3 ty ----------------
#pragma unroll
    for (int ty = 0; ty < 3; ++ty) {
        int slot = r_out + ty;           // input row index
        if (slot >= 3) slot -= 3;        // rotating slot
        const uint32_t ah_base = a_base0 + (uint32_t)slot * (A_SLOT * 2);
        const uint32_t al_base = ah_base + A_PLANE * 2;
        const uint32_t bt_base = b_base + (uint32_t)ty * (B_PLANE * 2);

#pragma unroll
        for (int ks = 0; ks < 12; ++ks) {
            const int tx   = ks >> 2;
            const int ci16 = ks & 3;

            uint32_t afr[2][2][4];     // [m16 half][plane hi/lo]
#pragma unroll
            for (int mt = 0; mt < 2; ++mt) {
                const int px = xw + mt * 16 + a_row_off + tx;
                const uint32_t off = (uint32_t)(px * (A_STRIDE * 2) + ci16 * 32 + a_kh);
                ldsm_x4(afr[mt][0], ah_base + off);
                ldsm_x4(afr[mt][1], al_base + off);
            }
            uint32_t bfr[2][4];        // [n16 group]
#pragma unroll
            for (int g = 0; g < 2; ++g) {
                const int n = wn * 32 + g * 16 + b_n_off;
                const uint32_t off = (uint32_t)(n * 400 + tx * 128 + ci16 * 32 + b_kh);
                ldsm_x4(bfr[g], bt_base + off);
            }
#pragma unroll
            for (int mt = 0; mt < 2; ++mt)
#pragma unroll
                for (int nt = 0; nt < 4; ++nt) {
                    const int g = nt >> 1, h2 = (nt & 1) * 2;
                    mma_f16(acc[mt][nt], afr[mt][0], bfr[g][h2], bfr[g][h2 + 1]);
                    mma_f16(acc[mt][nt], afr[mt][1], bfr[g][h2], bfr[g][h2 + 1]);
                }
        }

        if (ty == 0) {
            // slot0 (row y0-1) dead -> refill with row y0+2 for ty=2.
            __syncthreads();
            const int yy = y0 + 2;
            const bool rowok = (unsigned)yy < (unsigned)H;
#pragma unroll
            for (int q = 0; q < 5; ++q) {
                const int e = tid + q * CT;
                if (e >= 2080) break;
                const int px = e >> 4;
                const int c4 = (e & 15) << 2;
                float v0 = 0.f, v1 = 0.f, v2 = 0.f, v3 = 0.f;
                if (rowok && px >= 1 && px <= 128) {
                    v0 = fmaxf(fmaf(pr[q].x, s_scale[c4],     s_shift[c4]),     0.f);
                    v1 = fmaxf(fmaf(pr[q].y, s_scale[c4 + 1], s_shift[c4 + 1]), 0.f);
                    v2 = fmaxf(fmaf(pr[q].z, s_scale[c4 + 2], s_shift[c4 + 2]), 0.f);
                    v3 = fmaxf(fmaf(pr[q].w, s_scale[c4 + 3], s_shift[c4 + 3]), 0.f);
                }
                __half2 h01 = __floats2half2_rn(v0, v1);
                __half2 h23 = __floats2half2_rn(v2, v3);
                __half2 l01 = __floats2half2_rn(v0 - __low2float(h01), v1 - __high2float(h01));
                __half2 l23 = __floats2half2_rn(v2 - __low2float(h23), v3 - __high2float(h23));
                __half* slot0 = s_a;
                const int o = px * A_STRIDE + c4;
                *reinterpret_cast<uint2*>(slot0 + o) =
                    make_uint2(h2_bits(h01), h2_bits(h23));
                *reinterpret_cast<uint2*>(slot0 + A_PLANE + o) =
                    make_uint2(h2_bits(l01), h2_bits(l23));
            }
            // ty=1 reads slot1/slot2 only -> no barrier needed here.
        } else if (ty == 1) {
            __syncthreads();   // slot0 rewrite visible before ty=2 reads it
        }
    }

    // ---- epilogue: fp32 accumulators -> NHWC output ----
    const int ygl = y0 + r_out;
    float* ob = out + (((size_t)b * H + ygl) * W) * C;
#pragma unroll
    for (int mt = 0; mt < 2; ++mt) {
        const int x0 = xw + mt * 16 + (lane >> 2);
        float* row0 = ob + (size_t)x0 * C;
        float* row1 = row0 + 8 * C;
#pragma unroll
        for (int nt = 0; nt < 4; ++nt) {
            const int co = wn * 32 + nt * 8 + (lane & 3) * 2;
            *reinterpret_cast<float2*>(row0 + co) = make_float2(acc[mt][nt][0], acc[mt][nt][1]);
            *reinterpret_cast<float2*>(row1 + co) = make_float2(acc[mt][nt][2], acc[mt][nt][3]);
        }
    }
}

// ===========================================================================
// Fused diffusion v5: 1024 threads, consecutive-x mapping.
// Thread owns channel pair c=(tid&31)*2 at pixels x = (tid>>5)*4 + j, j=0..3.
// -> interior x-neighbors come from own registers (carry old values through
//    the j loop); only 2 boundary float2 LDS per thread per iteration.
// Coefficients BX,BY packed in one float4 array (1 LDS.128 per j).
// Channel-wrap offsets are per-thread constants (no per-j mask ALU).
// SMEM: P0, P1 (h ping/pong), CXY (packed coeffs) = 131,072 B.
// ===========================================================================
static constexpr int DIFF_SMEM_BYTES = 4 * 8192 * 4;   // 131,072 B
static constexpr int DTH = 1024;                        // diffuse threads

__global__ __launch_bounds__(DTH, 1)
void diffuse_fused(const float* __restrict__ f,
                   float* __restrict__ outh,
                   const float* __restrict__ g,
                   const float* __restrict__ gamma,
                   const float* __restrict__ beta,
                   const float* __restrict__ mean,
                   const float* __restrict__ var)
{
    extern __shared__ float sm[];
    float* P0  = sm;             // F, then h ping
    float* P1  = sm + 8192;      // G, then h pong
    float* CXY = sm + 16384;     // packed (bx.x,bx.y,by.x,by.y) per pair, 16384 floats
    __shared__ float sc[64], sh[64];

    const int tid = threadIdx.x;
    const int y   = blockIdx.x;
    const int b   = blockIdx.y;

    if (tid < 64) {
        float s = gamma[tid] * rsqrtf(var[tid] + EPS);
        sc[tid] = s;
        sh[tid] = beta[tid] - mean[tid] * s;
    }

    const size_t rowbase = (((size_t)b * H) + y) * W * C;
    const float* frow = f + rowbase;
    const float* grow = g + rowbase;
#pragma unroll
    for (int q = 0; q < 2; ++q) {
        const int idx = (tid + q * DTH) * 4;
        *reinterpret_cast<float4*>(P0 + idx) = *reinterpret_cast<const float4*>(frow + idx);
        *reinterpret_cast<float4*>(P1 + idx) = *reinterpret_cast<const float4*>(grow + idx);
    }
    __syncthreads();

    const int c  = (tid & 31) * 2;             // channel pair (c, c+1)
    const int xg = tid >> 5;                   // pixel group: x = xg*4 + j
    const int i0 = xg * 4 * 64 + c;            // element index of j=0
    const int ocm = ((c + 63) & 63) - c;       // offset to channel c-1 (wrapped)
    const int ocp = ((c + 2) & 63) - c;        // offset to channel c+2 (wrapped)
    const float2 sc2 = make_float2(sc[c], sc[c + 1]);
    const float2 sh2 = make_float2(sh[c], sh[c + 1]);

    const int ym = (y == 0) ? 1 : y - 1;
    const int yp = (y == H - 1) ? H - 2 : y + 1;
    const float* fm = f + ((((size_t)b * H) + ym) * W) * C;
    const float* fp = f + ((((size_t)b * H) + yp) * W) * C;

    float2 hprev[4], hcur[4], E2r[4], axr[4], cdr[4], cfr[4];

    // ---- setup: Sobel + all coefficients ----
#pragma unroll
    for (int j = 0; j < 4; ++j) {
        const int i = i0 + j * 64;
        const int x = xg * 4 + j;
        const int xm = (x == 0) ? 1 : x - 1;
        const int xp = (x == W - 1) ? W - 2 : x + 1;

        const float2 f2 = *reinterpret_cast<const float2*>(P0 + i);
        const float2 g2 = *reinterpret_cast<const float2*>(P1 + i);

        const float2 am = *reinterpret_cast<const float2*>(fm + xm * 64 + c);
        const float2 a0 = *reinterpret_cast<const float2*>(fm + x  * 64 + c);
        const float2 ap = *reinterpret_cast<const float2*>(fm + xp * 64 + c);
        const float2 bm = *reinterpret_cast<const float2*>(fp + xm * 64 + c);
        const float2 b0 = *reinterpret_cast<const float2*>(fp + x  * 64 + c);
        const float2 bp = *reinterpret_cast<const float2*>(fp + xp * 64 + c);
        const float2 fxm = *reinterpret_cast<const float2*>(P0 + xm * 64 + c);
        const float2 fxp = *reinterpret_cast<const float2*>(P0 + xp * 64 + c);

        float dyx = (bm.x + 2.f * b0.x + bp.x) - (am.x + 2.f * a0.x + ap.x);
        float dyy = (bm.y + 2.f * b0.y + bp.y) - (am.y + 2.f * a0.y + ap.y);
        float dxx = (ap.x - am.x) + 2.f * (fxp.x - fxm.x) + (bp.x - bm.x);
        float dxy = (ap.y - am.y) + 2.f * (fxp.y - fxm.y) + (bp.y - bm.y);

        float bxx = (2.f * DT) / (0.25f * dyx * dyx + 1.f);
        float bxy = (2.f * DT) / (0.25f * dyy * dyy + 1.f);
        float byx = (2.f * DT) / (0.25f * dxx * dxx + 1.f);
        float byy = (2.f * DT) / (0.25f * dxy * dxy + 1.f);
        *reinterpret_cast<float4*>(CXY + (i << 1)) = make_float4(bxx, bxy, byx, byy);

        cdr[j] = make_float2(1.f / (1.f + bxx + byx), 1.f / (1.f + bxy + byy));
        axr[j] = make_float2(DT * g2.x, DT * g2.y);
        cfr[j] = make_float2(2.f * DT * f2.x, 2.f * DT * f2.y);
        hprev[j] = f2;
        hcur[j]  = f2;

        // E2 = 2*E (P1 still holds G here)
        const int ixm = (i + 8192 - 64) & 8191;
        const int ixp = (i + 64) & 8191;
        const float2 gxm = *reinterpret_cast<const float2*>(P1 + ixm);
        const float2 gxp = *reinterpret_cast<const float2*>(P1 + ixp);
        const float gcm = P1[i + ocm];
        const float gcp = P1[i + ocp];
        E2r[j].x = DT * ((gxm.x - gxp.x) + (gcm - g2.y));
        E2r[j].y = DT * ((gxm.y - gxp.y) + (g2.x - gcp));
    }
    __syncthreads();

    // ---- K = 5 iterations; x-neighbors carried in registers ----
#pragma unroll
    for (int k = 0; k < 5; ++k) {
        float* rb = (k & 1) ? P1 : P0;
        float* wb = (k & 1) ? P0 : P1;

        // boundary x-neighbors (wrap): h_old[x = xg*4 - 1], h_old[x = xg*4 + 4]
        const int im = (i0 + 8192 - 64) & 8191;
        const int ip = (i0 + 256) & 8191;
        const float2 bxm = *reinterpret_cast<const float2*>(rb + im);
        const float2 bxp = *reinterpret_cast<const float2*>(rb + ip);

        float2 carry = bxm;                 // h_old at x-1 of current j
#pragma unroll
        for (int j = 0; j < 4; ++j) {
            const int i = i0 + j * 64;
            const float4 cxy = *reinterpret_cast<const float4*>(CXY + (i << 1));
            const float2 rxm = carry;
            const float2 rxp = (j == 3) ? bxp : hcur[j + 1];
            const float rcm = rb[i + ocm];
            const float rcp = rb[i + ocp];
            const float2 hc = hcur[j];
            const float2 ax = axr[j];

            float s0 = (1.f - cxy.x - cxy.z) * hprev[j].x;
            s0 = fmaf(-E2r[j].x, hc.x, s0);
            s0 = fmaf(cxy.x, rxm.x + rxp.x, s0);
            s0 = fmaf(ax.x,  rxp.x - rxm.x, s0);
            s0 = fmaf(cxy.z, rcm + hc.y, s0);
            s0 = fmaf(ax.x,  hc.y - rcm, s0);
            s0 = (s0 + cfr[j].x) * cdr[j].x;

            float s1 = (1.f - cxy.y - cxy.w) * hprev[j].y;
            s1 = fmaf(-E2r[j].y, hc.y, s1);
            s1 = fmaf(cxy.y, rxm.y + rxp.y, s1);
            s1 = fmaf(ax.y,  rxp.y - rxm.y, s1);
            s1 = fmaf(cxy.w, hc.x + rcp, s1);
            s1 = fmaf(ax.y,  rcp - hc.x, s1);
            s1 = (s1 + cfr[j].y) * cdr[j].y;

            carry = hc;                     // old value becomes x-1 for j+1
            hprev[j] = hc;
            hcur[j]  = make_float2(s0, s1);
            if (k < 4) *reinterpret_cast<float2*>(wb + i) = hcur[j];
        }
        if (k < 4) __syncthreads();
    }

    // ---- epilogue: relu(bn_o(h)) from registers ----
    float* o = outh + rowbase;
#pragma unroll
    for (int j = 0; j < 4; ++j) {
        const int i = i0 + j * 64;
        float2 r = make_float2(fmaxf(fmaf(hcur[j].x, sc2.x, sh2.x), 0.f),
                               fmaxf(fmaf(hcur[j].y, sc2.y, sh2.y), 0.f));
        *reinterpret_cast<float2*>(o + i) = r;
    }
}

// ===========================================================================
extern "C" void kernel_launch(void* const* d_in, const int* in_sizes, int n_in,
                              void* d_out, int out_size)
{
    const float* x   = (const float*)d_in[0];
    const float* f_w = (const float*)d_in[1];
    const float* g_w = (const float*)d_in[2];
    const float* bnf_gamma = (const float*)d_in[3];
    const float* bnf_beta  = (const float*)d_in[4];
    const float* bnf_mean  = (const float*)d_in[5];
    const float* bnf_var   = (const float*)d_in[6];
    const float* bng_gamma = (const float*)d_in[7];
    const float* bng_beta  = (const float*)d_in[8];
    const float* bng_mean  = (const float*)d_in[9];
    const float* bng_var   = (const float*)d_in[10];
    const float* bno_gamma = (const float*)d_in[11];
    const float* bno_beta  = (const float*)d_in[12];
    const float* bno_mean  = (const float*)d_in[13];
    const float* bno_var   = (const float*)d_in[14];

    float* out = (float*)d_out;            // [0:N) = h, [N:2N) = g

    float* fptr = nullptr;
    cudaGetSymbolAddress((void**)&fptr, d_f_buf);
    __half* wptr = nullptr;
    cudaGetSymbolAddress((void**)&wptr, d_wh);

    cudaFuncSetAttribute(conv_mma,
                         cudaFuncAttributeMaxDynamicSharedMemorySize, CONV_SMEM_BYTES);
    cudaFuncSetAttribute(diffuse_fused,
                         cudaFuncAttributeMaxDynamicSharedMemorySize, DIFF_SMEM_BYTES);

    // 1) weight transform (both convs)
    prep_weights<<<288, 256>>>(f_w, g_w);

    dim3 cgrid(H / 2, B);

    // 2) f = conv(relu(bn_f(x)), f_w)
    conv_mma<<<cgrid, CT, CONV_SMEM_BYTES>>>(
        x, wptr, bnf_gamma, bnf_beta, bnf_mean, bnf_var, fptr);

    // 3) g = conv(relu(bn_g(f)), g_w) -> d_out[N:2N)
    conv_mma<<<cgrid, CT, CONV_SMEM_BYTES>>>(
        fptr, wptr + 3 * B_PLANE, bng_gamma, bng_beta, bng_mean, bng_var, out + NTOT);

    // 4) fused sobel + coefficients + 5 diffusion iters + bn_o/relu -> d_out[0:N)
    dim3 dgrid(H, B);
    diffuse_fused<<<dgrid, DTH, DIFF_SMEM_BYTES>>>(
        fptr, out, out + NTOT, bno_gamma, bno_beta, bno_mean, bno_var);
}

// round 16
// speedup vs baseline: 1.7182x; 1.2909x over previous
#include <cuda_runtime.h>
#include <cuda_fp16.h>
#include <cstdint>

// ===========================================================================
// Problem constants
// ===========================================================================
static constexpr int B  = 16;
static constexpr int H  = 128;
static constexpr int W  = 128;
static constexpr int C  = 64;
static constexpr int NTOT = B * H * W * C;    // 16,777,216
static constexpr float DT  = 0.2f;
static constexpr float EPS = 1e-3f;

// Scratch
__device__ float d_f_buf[NTOT];               // conv1 output (f == h_init)
// fp16 weights, single plane: [conv][ty][n*200 + k], k = tx*64 + ci
__device__ __half d_wh[2][3][64 * 200];

// ===========================================================================
// PTX helpers (plain-PTX, valid on .target sm_103)
// ===========================================================================
__device__ __forceinline__ uint32_t smem_u32(const void* p) {
    uint32_t a;
    asm("{ .reg .u64 t; cvta.to.shared.u64 t, %1; cvt.u32.u64 %0, t; }"
        : "=r"(a) : "l"(p));
    return a;
}

__device__ __forceinline__ void ldsm_x4(uint32_t (&r)[4], uint32_t addr) {
    asm volatile("ldmatrix.sync.aligned.m8n8.x4.shared.b16 {%0,%1,%2,%3}, [%4];"
                 : "=r"(r[0]), "=r"(r[1]), "=r"(r[2]), "=r"(r[3]) : "r"(addr));
}

__device__ __forceinline__ void mma_f16(float (&d)[4], const uint32_t (&a)[4],
                                        uint32_t b0, uint32_t b1) {
    asm volatile(
        "mma.sync.aligned.m16n8k16.row.col.f32.f16.f16.f32 "
        "{%0,%1,%2,%3}, {%4,%5,%6,%7}, {%8,%9}, {%0,%1,%2,%3};"
        : "+f"(d[0]), "+f"(d[1]), "+f"(d[2]), "+f"(d[3])
        : "r"(a[0]), "r"(a[1]), "r"(a[2]), "r"(a[3]), "r"(b0), "r"(b1));
}

__device__ __forceinline__ void cp_async16(uint32_t saddr, const void* gaddr) {
    asm volatile("cp.async.cg.shared.global [%0], [%1], 16;"
                 :: "r"(saddr), "l"(gaddr) : "memory");
}
__device__ __forceinline__ void cp_commit() {
    asm volatile("cp.async.commit_group;" ::: "memory");
}
template <int N>
__device__ __forceinline__ void cp_wait() {
    asm volatile("cp.async.wait_group %0;" :: "n"(N) : "memory");
}

__device__ __forceinline__ uint32_t h2_bits(__half2 v) {
    uint32_t u;
    memcpy(&u, &v, 4);
    return u;
}

// ===========================================================================
// Weight prep: HWIO [3][3][64][64] -> per-ty [N=64][K=192] fp16 (single
// plane), rows padded to 200 halfs (400 B).
// ===========================================================================
__global__ void prep_weights(const float* __restrict__ fw,
                             const float* __restrict__ gw)
{
    int idx = blockIdx.x * blockDim.x + threadIdx.x;     // 2*3*192*64 = 73728
    if (idx >= 73728) return;
    int conv = idx / 36864;  int r = idx - conv * 36864;
    int ty   = r / 12288;    r -= ty * 12288;
    int k    = r >> 6;       int n = r & 63;             // k 0..191, n = cout
    int tx   = k >> 6;       int ci = k & 63;
    const float* w = conv ? gw : fw;
    float v = w[(((ty * 3 + tx) * 64) + ci) * 64 + n];
    d_wh[conv][ty][n * 200 + k] = __float2half_rn(v);
}

// ===========================================================================
// Conv v6: 1-pass fp16 (A single fp16 plane, B single fp16 plane),
// 2 output rows per block (M=256), 2 CTAs/SM.
// Grid (64, 16); 512 threads / 16 warps as 8(m) x 2(n): warp tile m32 x n32.
// A: rows y0-1..y0+2 in 3 rotating single-plane slots.
// B: 2 cp.async double-buffered ty planes (B0,B1 upfront; B2 after ty0).
// SMEM: 3*9360*2 + 2*12800*2 = 107,360 B -> 2 CTAs/SM (32 warps).
// ===========================================================================
static constexpr int A_STRIDE = 72;
static constexpr int A_PLANE  = 130 * A_STRIDE;           // 9360 halfs (1 plane)
static constexpr int B_PLANE  = 64 * 200;                 // 12800 halfs per ty
static constexpr int CONV_SMEM_BYTES = (3 * A_PLANE + 2 * B_PLANE) * 2;  // 107,360
static constexpr int CT = 512;

__global__ __launch_bounds__(CT, 2)
void conv_mma(const float* __restrict__ in,
              const __half* __restrict__ wbase,           // d_wh[conv]
              const float* __restrict__ gamma,
              const float* __restrict__ beta,
              const float* __restrict__ mean,
              const float* __restrict__ var,
              float* __restrict__ out)
{
    extern __shared__ __align__(16) char smem_raw[];
    __half* s_a = reinterpret_cast<__half*>(smem_raw);    // 3 single-plane slots
    __half* s_b = s_a + 3 * A_PLANE;                      // 2 B buffers
    __shared__ float s_scale[64], s_shift[64];

    const int tid  = threadIdx.x;
    const int wid  = tid >> 5;
    const int lane = tid & 31;
    const int y0   = blockIdx.x * 2;
    const int b    = blockIdx.y;
    const int wm   = wid & 7;        // m32 tile over 256 px
    const int wn   = wid >> 3;       // n32 tile over 64 couts
    const int r_out = wm >> 2;       // output row within block (0/1)
    const int xw    = (wm & 3) * 32; // x offset of warp tile

    if (tid < 64) {
        float sc = gamma[tid] * rsqrtf(var[tid] + EPS);
        s_scale[tid] = sc;
        s_shift[tid] = beta[tid] - mean[tid] * sc;
    }

    const uint32_t a_base0 = smem_u32(s_a);
    const uint32_t b_base  = smem_u32(s_b);

    // ---- issue cp.async for B ty=0 (buf0, group0) and ty=1 (buf1, group1) ----
#pragma unroll
    for (int tyg = 0; tyg < 2; ++tyg) {
        const char* src = reinterpret_cast<const char*>(wbase + tyg * B_PLANE);
        const uint32_t dst = b_base + (uint32_t)tyg * (B_PLANE * 2);
#pragma unroll
        for (int q = 0; q < 4; ++q) {
            int idx = tid + q * CT;
            if (idx < 1600) cp_async16(dst + idx * 16, src + idx * 16);
        }
        cp_commit();
    }

    const float* inb = in + ((size_t)b * H) * W * C;

    const int r8  = lane & 7;
    const int sel = lane >> 3;
    const int a_row_off = (sel & 1) * 8 + r8;
    const int a_kh      = (sel >> 1) * 16;
    const int b_n_off   = (sel >> 1) * 8 + r8;
    const int b_kh      = (sel & 1) * 16;

    __syncthreads();   // s_scale/s_shift ready

    // ---- stage input rows y0-1, y0, y0+1 into slots 0,1,2 (fp16 hi only) ----
#pragma unroll
    for (int q = 0; q < 13; ++q) {
        const int idx = tid + q * CT;
        if (idx >= 6240) break;
        const int r  = idx / 2080;
        const int e  = idx - r * 2080;
        const int px = e >> 4;
        const int c4 = (e & 15) << 2;
        const int yy = y0 - 1 + r;
        float v0 = 0.f, v1 = 0.f, v2 = 0.f, v3 = 0.f;
        if ((unsigned)yy < (unsigned)H && px >= 1 && px <= 128) {
            float4 t = *reinterpret_cast<const float4*>(
                inb + ((size_t)yy * W + (px - 1)) * C + c4);
            v0 = fmaxf(fmaf(t.x, s_scale[c4],     s_shift[c4]),     0.f);
            v1 = fmaxf(fmaf(t.y, s_scale[c4 + 1], s_shift[c4 + 1]), 0.f);
            v2 = fmaxf(fmaf(t.z, s_scale[c4 + 2], s_shift[c4 + 2]), 0.f);
            v3 = fmaxf(fmaf(t.w, s_scale[c4 + 3], s_shift[c4 + 3]), 0.f);
        }
        __half2 h01 = __floats2half2_rn(v0, v1);
        __half2 h23 = __floats2half2_rn(v2, v3);
        *reinterpret_cast<uint2*>(s_a + r * A_PLANE + px * A_STRIDE + c4) =
            make_uint2(h2_bits(h01), h2_bits(h23));
    }
    cp_wait<0>();      // B0, B1 arrived
    __syncthreads();

    float acc[2][4][4];            // [m16 half][n8 quarter]
#pragma unroll
    for (int mt = 0; mt < 2; ++mt)
#pragma unroll
        for (int nt = 0; nt < 4; ++nt)
#pragma unroll
            for (int e = 0; e < 4; ++e) acc[mt][nt][e] = 0.f;

    // ---------------- mma over 3 ty ----------------
#pragma unroll
    for (int ty = 0; ty < 3; ++ty) {
        int slot = r_out + ty;           // input row index
        if (slot >= 3) slot -= 3;        // rotating slot
        const uint32_t ah_base = a_base0 + (uint32_t)slot * (A_PLANE * 2);
        const int bbuf = (ty == 1) ? 1 : 0;    // ty0->buf0, ty1->buf1, ty2->buf0
        const uint32_t bt_base = b_base + (uint32_t)bbuf * (B_PLANE * 2);

#pragma unroll
        for (int ks = 0; ks < 12; ++ks) {
            const int tx   = ks >> 2;
            const int ci16 = ks & 3;

            uint32_t afr[2][4];        // [m16 half]
#pragma unroll
            for (int mt = 0; mt < 2; ++mt) {
                const int px = xw + mt * 16 + a_row_off + tx;
                ldsm_x4(afr[mt], ah_base +
                        (uint32_t)(px * (A_STRIDE * 2) + ci16 * 32 + a_kh));
            }
            uint32_t bfr[2][4];        // [n16 group]
#pragma unroll
            for (int g = 0; g < 2; ++g) {
                const int n = wn * 32 + g * 16 + b_n_off;
                ldsm_x4(bfr[g], bt_base +
                        (uint32_t)(n * 400 + tx * 128 + ci16 * 32 + b_kh));
            }
#pragma unroll
            for (int mt = 0; mt < 2; ++mt)
#pragma unroll
                for (int nt = 0; nt < 4; ++nt) {
                    const int g = nt >> 1, h2 = (nt & 1) * 2;
                    mma_f16(acc[mt][nt], afr[mt], bfr[g][h2], bfr[g][h2 + 1]);
                }
        }

        if (ty == 0) {
            // slot0 (row y0-1) dead; buf0 dead. Refill both for ty=2.
            __syncthreads();
            // transform row y0+2 into slot 0 (direct global load; the second
            // CTA on this SM hides the latency)
            const int yy = y0 + 2;
            const bool rowok = (unsigned)yy < (unsigned)H;
#pragma unroll
            for (int q = 0; q < 5; ++q) {
                const int e = tid + q * CT;
                if (e >= 2080) break;
                const int px = e >> 4;
                const int c4 = (e & 15) << 2;
                float v0 = 0.f, v1 = 0.f, v2 = 0.f, v3 = 0.f;
                if (rowok && px >= 1 && px <= 128) {
                    float4 t = *reinterpret_cast<const float4*>(
                        inb + ((size_t)yy * W + (px - 1)) * C + c4);
                    v0 = fmaxf(fmaf(t.x, s_scale[c4],     s_shift[c4]),     0.f);
                    v1 = fmaxf(fmaf(t.y, s_scale[c4 + 1], s_shift[c4 + 1]), 0.f);
                    v2 = fmaxf(fmaf(t.z, s_scale[c4 + 2], s_shift[c4 + 2]), 0.f);
                    v3 = fmaxf(fmaf(t.w, s_scale[c4 + 3], s_shift[c4 + 3]), 0.f);
                }
                __half2 h01 = __floats2half2_rn(v0, v1);
                __half2 h23 = __floats2half2_rn(v2, v3);
                *reinterpret_cast<uint2*>(s_a + px * A_STRIDE + c4) =
                    make_uint2(h2_bits(h01), h2_bits(h23));
            }
            // B ty=2 into buf0 (group2)
            {
                const char* src = reinterpret_cast<const char*>(wbase + 2 * B_PLANE);
#pragma unroll
                for (int q = 0; q < 4; ++q) {
                    int idx = tid + q * CT;
                    if (idx < 1600) cp_async16(b_base + idx * 16, src + idx * 16);
                }
                cp_commit();
            }
            // ty=1 uses slot1/slot2 + buf1: all ready; no barrier needed here.
        } else if (ty == 1) {
            cp_wait<0>();      // B2 arrived
            __syncthreads();   // slot0 rewrite + B2 visible to all
        }
    }

    // ---- epilogue: fp32 accumulators -> NHWC output ----
    const int ygl = y0 + r_out;
    float* ob = out + (((size_t)b * H + ygl) * W) * C;
#pragma unroll
    for (int mt = 0; mt < 2; ++mt) {
        const int x0 = xw + mt * 16 + (lane >> 2);
        float* row0 = ob + (size_t)x0 * C;
        float* row1 = row0 + 8 * C;
#pragma unroll
        for (int nt = 0; nt < 4; ++nt) {
            const int co = wn * 32 + nt * 8 + (lane & 3) * 2;
            *reinterpret_cast<float2*>(row0 + co) = make_float2(acc[mt][nt][0], acc[mt][nt][1]);
            *reinterpret_cast<float2*>(row1 + co) = make_float2(acc[mt][nt][2], acc[mt][nt][3]);
        }
    }
}

// ===========================================================================
// Fused diffusion v5 (unchanged from R15): 1024 threads, consecutive-x
// mapping, x-neighbors carried in registers, packed float4 coefficients.
// ===========================================================================
static constexpr int DIFF_SMEM_BYTES = 4 * 8192 * 4;   // 131,072 B
static constexpr int DTH = 1024;

__global__ __launch_bounds__(DTH, 1)
void diffuse_fused(const float* __restrict__ f,
                   float* __restrict__ outh,
                   const float* __restrict__ g,
                   const float* __restrict__ gamma,
                   const float* __restrict__ beta,
                   const float* __restrict__ mean,
                   const float* __restrict__ var)
{
    extern __shared__ float sm[];
    float* P0  = sm;             // F, then h ping
    float* P1  = sm + 8192;      // G, then h pong
    float* CXY = sm + 16384;     // packed (bx.x,bx.y,by.x,by.y) per pair
    __shared__ float sc[64], sh[64];

    const int tid = threadIdx.x;
    const int y   = blockIdx.x;
    const int b   = blockIdx.y;

    if (tid < 64) {
        float s = gamma[tid] * rsqrtf(var[tid] + EPS);
        sc[tid] = s;
        sh[tid] = beta[tid] - mean[tid] * s;
    }

    const size_t rowbase = (((size_t)b * H) + y) * W * C;
    const float* frow = f + rowbase;
    const float* grow = g + rowbase;
#pragma unroll
    for (int q = 0; q < 2; ++q) {
        const int idx = (tid + q * DTH) * 4;
        *reinterpret_cast<float4*>(P0 + idx) = *reinterpret_cast<const float4*>(frow + idx);
        *reinterpret_cast<float4*>(P1 + idx) = *reinterpret_cast<const float4*>(grow + idx);
    }
    __syncthreads();

    const int c  = (tid & 31) * 2;             // channel pair (c, c+1)
    const int xg = tid >> 5;                   // pixel group: x = xg*4 + j
    const int i0 = xg * 4 * 64 + c;            // element index of j=0
    const int ocm = ((c + 63) & 63) - c;       // offset to channel c-1 (wrapped)
    const int ocp = ((c + 2) & 63) - c;        // offset to channel c+2 (wrapped)
    const float2 sc2 = make_float2(sc[c], sc[c + 1]);
    const float2 sh2 = make_float2(sh[c], sh[c + 1]);

    const int ym = (y == 0) ? 1 : y - 1;
    const int yp = (y == H - 1) ? H - 2 : y + 1;
    const float* fm = f + ((((size_t)b * H) + ym) * W) * C;
    const float* fp = f + ((((size_t)b * H) + yp) * W) * C;

    float2 hprev[4], hcur[4], E2r[4], axr[4], cdr[4], cfr[4];

    // ---- setup: Sobel + all coefficients ----
#pragma unroll
    for (int j = 0; j < 4; ++j) {
        const int i = i0 + j * 64;
        const int x = xg * 4 + j;
        const int xm = (x == 0) ? 1 : x - 1;
        const int xp = (x == W - 1) ? W - 2 : x + 1;

        const float2 f2 = *reinterpret_cast<const float2*>(P0 + i);
        const float2 g2 = *reinterpret_cast<const float2*>(P1 + i);

        const float2 am = *reinterpret_cast<const float2*>(fm + xm * 64 + c);
        const float2 a0 = *reinterpret_cast<const float2*>(fm + x  * 64 + c);
        const float2 ap = *reinterpret_cast<const float2*>(fm + xp * 64 + c);
        const float2 bm = *reinterpret_cast<const float2*>(fp + xm * 64 + c);
        const float2 b0 = *reinterpret_cast<const float2*>(fp + x  * 64 + c);
        const float2 bp = *reinterpret_cast<const float2*>(fp + xp * 64 + c);
        const float2 fxm = *reinterpret_cast<const float2*>(P0 + xm * 64 + c);
        const float2 fxp = *reinterpret_cast<const float2*>(P0 + xp * 64 + c);

        float dyx = (bm.x + 2.f * b0.x + bp.x) - (am.x + 2.f * a0.x + ap.x);
        float dyy = (bm.y + 2.f * b0.y + bp.y) - (am.y + 2.f * a0.y + ap.y);
        float dxx = (ap.x - am.x) + 2.f * (fxp.x - fxm.x) + (bp.x - bm.x);
        float dxy = (ap.y - am.y) + 2.f * (fxp.y - fxm.y) + (bp.y - bm.y);

        float bxx = (2.f * DT) / (0.25f * dyx * dyx + 1.f);
        float bxy = (2.f * DT) / (0.25f * dyy * dyy + 1.f);
        float byx = (2.f * DT) / (0.25f * dxx * dxx + 1.f);
        float byy = (2.f * DT) / (0.25f * dxy * dxy + 1.f);
        *reinterpret_cast<float4*>(CXY + (i << 1)) = make_float4(bxx, bxy, byx, byy);

        cdr[j] = make_float2(1.f / (1.f + bxx + byx), 1.f / (1.f + bxy + byy));
        axr[j] = make_float2(DT * g2.x, DT * g2.y);
        cfr[j] = make_float2(2.f * DT * f2.x, 2.f * DT * f2.y);
        hprev[j] = f2;
        hcur[j]  = f2;

        const int ixm = (i + 8192 - 64) & 8191;
        const int ixp = (i + 64) & 8191;
        const float2 gxm = *reinterpret_cast<const float2*>(P1 + ixm);
        const float2 gxp = *reinterpret_cast<const float2*>(P1 + ixp);
        const float gcm = P1[i + ocm];
        const float gcp = P1[i + ocp];
        E2r[j].x = DT * ((gxm.x - gxp.x) + (gcm - g2.y));
        E2r[j].y = DT * ((gxm.y - gxp.y) + (g2.x - gcp));
    }
    __syncthreads();

    // ---- K = 5 iterations; x-neighbors carried in registers ----
#pragma unroll
    for (int k = 0; k < 5; ++k) {
        float* rb = (k & 1) ? P1 : P0;
        float* wb = (k & 1) ? P0 : P1;

        const int im = (i0 + 8192 - 64) & 8191;
        const int ip = (i0 + 256) & 8191;
        const float2 bxm = *reinterpret_cast<const float2*>(rb + im);
        const float2 bxp = *reinterpret_cast<const float2*>(rb + ip);

        float2 carry = bxm;
#pragma unroll
        for (int j = 0; j < 4; ++j) {
            const int i = i0 + j * 64;
            const float4 cxy = *reinterpret_cast<const float4*>(CXY + (i << 1));
            const float2 rxm = carry;
            const float2 rxp = (j == 3) ? bxp : hcur[j + 1];
            const float rcm = rb[i + ocm];
            const float rcp = rb[i + ocp];
            const float2 hc = hcur[j];
            const float2 ax = axr[j];

            float s0 = (1.f - cxy.x - cxy.z) * hprev[j].x;
            s0 = fmaf(-E2r[j].x, hc.x, s0);
            s0 = fmaf(cxy.x, rxm.x + rxp.x, s0);
            s0 = fmaf(ax.x,  rxp.x - rxm.x, s0);
            s0 = fmaf(cxy.z, rcm + hc.y, s0);
            s0 = fmaf(ax.x,  hc.y - rcm, s0);
            s0 = (s0 + cfr[j].x) * cdr[j].x;

            float s1 = (1.f - cxy.y - cxy.w) * hprev[j].y;
            s1 = fmaf(-E2r[j].y, hc.y, s1);
            s1 = fmaf(cxy.y, rxm.y + rxp.y, s1);
            s1 = fmaf(ax.y,  rxp.y - rxm.y, s1);
            s1 = fmaf(cxy.w, hc.x + rcp, s1);
            s1 = fmaf(ax.y,  rcp - hc.x, s1);
            s1 = (s1 + cfr[j].y) * cdr[j].y;

            carry = hc;
            hprev[j] = hc;
            hcur[j]  = make_float2(s0, s1);
            if (k < 4) *reinterpret_cast<float2*>(wb + i) = hcur[j];
        }
        if (k < 4) __syncthreads();
    }

    // ---- epilogue: relu(bn_o(h)) from registers ----
    float* o = outh + rowbase;
#pragma unroll
    for (int j = 0; j < 4; ++j) {
        const int i = i0 + j * 64;
        float2 r = make_float2(fmaxf(fmaf(hcur[j].x, sc2.x, sh2.x), 0.f),
                               fmaxf(fmaf(hcur[j].y, sc2.y, sh2.y), 0.f));
        *reinterpret_cast<float2*>(o + i) = r;
    }
}

// ===========================================================================
extern "C" void kernel_launch(void* const* d_in, const int* in_sizes, int n_in,
                              void* d_out, int out_size)
{
    const float* x   = (const float*)d_in[0];
    const float* f_w = (const float*)d_in[1];
    const float* g_w = (const float*)d_in[2];
    const float* bnf_gamma = (const float*)d_in[3];
    const float* bnf_beta  = (const float*)d_in[4];
    const float* bnf_mean  = (const float*)d_in[5];
    const float* bnf_var   = (const float*)d_in[6];
    const float* bng_gamma = (const float*)d_in[7];
    const float* bng_beta  = (const float*)d_in[8];
    const float* bng_mean  = (const float*)d_in[9];
    const float* bng_var   = (const float*)d_in[10];
    const float* bno_gamma = (const float*)d_in[11];
    const float* bno_beta  = (const float*)d_in[12];
    const float* bno_mean  = (const float*)d_in[13];
    const float* bno_var   = (const float*)d_in[14];

    float* out = (float*)d_out;            // [0:N) = h, [N:2N) = g

    float* fptr = nullptr;
    cudaGetSymbolAddress((void**)&fptr, d_f_buf);
    __half* wptr = nullptr;
    cudaGetSymbolAddress((void**)&wptr, d_wh);

    cudaFuncSetAttribute(conv_mma,
                         cudaFuncAttributeMaxDynamicSharedMemorySize, CONV_SMEM_BYTES);
    cudaFuncSetAttribute(diffuse_fused,
                         cudaFuncAttributeMaxDynamicSharedMemorySize, DIFF_SMEM_BYTES);

    // 1) weight transform (both convs)
    prep_weights<<<288, 256>>>(f_w, g_w);

    dim3 cgrid(H / 2, B);

    // 2) f = conv(relu(bn_f(x)), f_w)
    conv_mma<<<cgrid, CT, CONV_SMEM_BYTES>>>(
        x, wptr, bnf_gamma, bnf_beta, bnf_mean, bnf_var, fptr);

    // 3) g = conv(relu(bn_g(f)), g_w) -> d_out[N:2N)
    conv_mma<<<cgrid, CT, CONV_SMEM_BYTES>>>(
        fptr, wptr + 3 * B_PLANE, bng_gamma, bng_beta, bng_mean, bng_var, out + NTOT);

    // 4) fused sobel + coefficients + 5 diffusion iters + bn_o/relu -> d_out[0:N)
    dim3 dgrid(H, B);
    diffuse_fused<<<dgrid, DTH, DIFF_SMEM_BYTES>>>(
        fptr, out, out + NTOT, bno_gamma, bno_beta, bno_mean, bno_var);
}